// round 3
// baseline (speedup 1.0000x reference)
#include <cuda_runtime.h>
#include <math.h>

// ---------------------------------------------------------------------------
// SwinBlock3D: x(1,384,16,64,64), GRID=(4,8,8), SHIFT=(2,4,4), HEADS=6, MLP=1536
// 65536 tokens x 384 ch; 256 windows x 256 tokens; dh=64.
// All heavy math in packed f32x2 (FFMA2) for 2x fp32 throughput on sm_103a.
// ---------------------------------------------------------------------------

#define NTOK 65536
#define CDIM 384
#define MLPD 1536

// scratch (device globals: no allocation allowed)
__device__ float g_xw [(size_t)NTOK * CDIM];
__device__ float g_h  [(size_t)NTOK * CDIM];
__device__ float g_q  [(size_t)NTOK * CDIM];
__device__ float g_k  [(size_t)NTOK * CDIM];
__device__ float g_v  [(size_t)NTOK * CDIM];
__device__ float g_att[(size_t)NTOK * CDIM];
__device__ float g_x2 [(size_t)NTOK * CDIM];
__device__ float g_mlp[(size_t)NTOK * MLPD];

// ---------------- packed f32x2 helpers -------------------------------------
__device__ __forceinline__ unsigned long long pk2(float lo, float hi) {
    unsigned long long r;
    unsigned int a = __float_as_uint(lo), b = __float_as_uint(hi);
    asm("mov.b64 %0, {%1, %2};" : "=l"(r) : "r"(a), "r"(b));
    return r;
}
__device__ __forceinline__ void upk2(unsigned long long p, float &lo, float &hi) {
    unsigned int a, b;
    asm("mov.b64 {%0, %1}, %2;" : "=r"(a), "=r"(b) : "l"(p));
    lo = __uint_as_float(a); hi = __uint_as_float(b);
}
__device__ __forceinline__ unsigned long long fma2(unsigned long long a,
                                                   unsigned long long b,
                                                   unsigned long long c) {
    unsigned long long d;
    asm("fma.rn.f32x2 %0, %1, %2, %3;" : "=l"(d) : "l"(a), "l"(b), "l"(c));
    return d;
}
__device__ __forceinline__ unsigned long long add2(unsigned long long a,
                                                   unsigned long long b) {
    unsigned long long d;
    asm("add.rn.f32x2 %0, %1, %2;" : "=l"(d) : "l"(a), "l"(b));
    return d;
}
__device__ __forceinline__ unsigned long long mul2(unsigned long long a,
                                                   unsigned long long b) {
    unsigned long long d;
    asm("mul.rn.f32x2 %0, %1, %2;" : "=l"(d) : "l"(a), "l"(b));
    return d;
}

// ---------------- shift + window partition (gather) -------------------------
// xw[n, c] = x[c, d0, h0, w0] where (d,h,w)=((d0-2)%16,(h0-4)%64,(w0-4)%64),
// n = window(d,h,w)*256 + token(d,h,w)
__device__ __forceinline__ int token_index(int d, int h, int w) {
    int win = ((d >> 2) * 8 + (h >> 3)) * 8 + (w >> 3);
    int tok = ((d & 3) << 6) + ((h & 7) << 3) + (w & 7);
    return (win << 8) + tok;
}

__global__ void window_gather_kernel(const float* __restrict__ x,
                                     float* __restrict__ xw) {
    __shared__ float sm[32][65];
    const int c0 = blockIdx.x * 32;
    const int h0 = blockIdx.y;
    const int d0 = blockIdx.z;
    const int tid = threadIdx.x;
    {
        int cl = tid >> 4;
        int v4 = (tid & 15) * 4;
        const float* xp = x + (size_t)(c0 + cl) * 65536 + d0 * 4096 + h0 * 64 + v4;
        float4 a = *(const float4*)xp;
        sm[cl][v4 + 0] = a.x; sm[cl][v4 + 1] = a.y;
        sm[cl][v4 + 2] = a.z; sm[cl][v4 + 3] = a.w;
        float4 b = *(const float4*)(xp + (size_t)16 * 65536);
        sm[cl + 16][v4 + 0] = b.x; sm[cl + 16][v4 + 1] = b.y;
        sm[cl + 16][v4 + 2] = b.z; sm[cl + 16][v4 + 3] = b.w;
    }
    __syncthreads();
    int w0 = tid >> 2;
    int cg = (tid & 3) * 8;
    int d = (d0 + 14) & 15;
    int h = (h0 + 60) & 63;
    int w = (w0 + 60) & 63;
    int n = token_index(d, h, w);
    float* op = xw + (size_t)n * CDIM + c0 + cg;
    float4 o0, o1;
    o0.x = sm[cg + 0][w0]; o0.y = sm[cg + 1][w0];
    o0.z = sm[cg + 2][w0]; o0.w = sm[cg + 3][w0];
    o1.x = sm[cg + 4][w0]; o1.y = sm[cg + 5][w0];
    o1.z = sm[cg + 6][w0]; o1.w = sm[cg + 7][w0];
    *(float4*)op = o0;
    *(float4*)(op + 4) = o1;
}

__global__ void window_scatter_kernel(const float* __restrict__ y,
                                      float* __restrict__ out) {
    __shared__ float sm[32][65];
    const int c0 = blockIdx.x * 32;
    const int h0 = blockIdx.y;
    const int d0 = blockIdx.z;
    const int tid = threadIdx.x;
    {
        int w0 = tid >> 2;
        int cg = (tid & 3) * 8;
        int d = (d0 + 14) & 15;
        int h = (h0 + 60) & 63;
        int w = (w0 + 60) & 63;
        int n = token_index(d, h, w);
        const float* ip = y + (size_t)n * CDIM + c0 + cg;
        float4 a = *(const float4*)ip;
        float4 b = *(const float4*)(ip + 4);
        sm[cg + 0][w0] = a.x; sm[cg + 1][w0] = a.y;
        sm[cg + 2][w0] = a.z; sm[cg + 3][w0] = a.w;
        sm[cg + 4][w0] = b.x; sm[cg + 5][w0] = b.y;
        sm[cg + 6][w0] = b.z; sm[cg + 7][w0] = b.w;
    }
    __syncthreads();
    int cl = tid >> 4;
    int v4 = (tid & 15) * 4;
    float* op = out + (size_t)(c0 + cl) * 65536 + d0 * 4096 + h0 * 64 + v4;
    float4 o;
    o.x = sm[cl][v4 + 0]; o.y = sm[cl][v4 + 1];
    o.z = sm[cl][v4 + 2]; o.w = sm[cl][v4 + 3];
    *(float4*)op = o;
    float4 p;
    p.x = sm[cl + 16][v4 + 0]; p.y = sm[cl + 16][v4 + 1];
    p.z = sm[cl + 16][v4 + 2]; p.w = sm[cl + 16][v4 + 3];
    *(float4*)(op + (size_t)16 * 65536) = p;
}

// ---------------- layernorm: one warp per token -----------------------------
__global__ void ln_kernel(const float* __restrict__ x,
                          const float* __restrict__ gam,
                          const float* __restrict__ bet,
                          float* __restrict__ out) {
    int warp = threadIdx.x >> 5;
    int lane = threadIdx.x & 31;
    size_t n = (size_t)blockIdx.x * 8 + warp;
    const float4* xr = (const float4*)(x + n * CDIM);
    float4 v[3];
    float s = 0.f, ss = 0.f;
#pragma unroll
    for (int i = 0; i < 3; i++) {
        v[i] = xr[i * 32 + lane];
        s += v[i].x + v[i].y + v[i].z + v[i].w;
        ss += v[i].x * v[i].x + v[i].y * v[i].y + v[i].z * v[i].z + v[i].w * v[i].w;
    }
#pragma unroll
    for (int off = 16; off; off >>= 1) {
        s  += __shfl_xor_sync(0xffffffffu, s,  off);
        ss += __shfl_xor_sync(0xffffffffu, ss, off);
    }
    float mean = s * (1.0f / CDIM);
    float var  = ss * (1.0f / CDIM) - mean * mean;
    float rstd = rsqrtf(var + 1e-5f);
    const float4* G = (const float4*)gam;
    const float4* B = (const float4*)bet;
    float4* o = (float4*)(out + n * CDIM);
#pragma unroll
    for (int i = 0; i < 3; i++) {
        float4 g = G[i * 32 + lane];
        float4 b = B[i * 32 + lane];
        float4 r;
        r.x = (v[i].x - mean) * rstd * g.x + b.x;
        r.y = (v[i].y - mean) * rstd * g.y + b.y;
        r.z = (v[i].z - mean) * rstd * g.z + b.z;
        r.w = (v[i].w - mean) * rstd * g.w + b.w;
        o[i * 32 + lane] = r;
    }
}

// ---------------- packed-f32x2 SGEMM core (128x128x16, 8x8/thread) ----------
// A:[rows,K] row-major, B:[K,ldb] row-major. acc lanes: lo=row ty*8+2p, hi=+1.
__device__ __forceinline__ void sgemm_core(const float* __restrict__ A,
                                           const float* __restrict__ B,
                                           int K, int ldb,
                                           int rowTile, int colTile,
                                           unsigned long long acc[4][8]) {
    __shared__ float As[16][128];
    __shared__ float Bs[16][128];
    const int tid = threadIdx.x;
    const int tx = tid & 15, ty = tid >> 4;
    const int aRow = tid >> 2;
    const int aK = (tid & 3) * 4;
    const int bK = tid >> 5;
    const int bN = (tid & 31) * 4;

    const float* Aptr = A + (size_t)rowTile * 128 * K;
    const float* Bptr = B + colTile * 128;

#pragma unroll
    for (int p = 0; p < 4; p++)
#pragma unroll
        for (int j = 0; j < 8; j++) acc[p][j] = 0ULL;

    for (int k0 = 0; k0 < K; k0 += 16) {
#pragma unroll
        for (int hh = 0; hh < 2; hh++) {
            int r = aRow + hh * 64;
            float4 av = *(const float4*)(Aptr + (size_t)r * K + k0 + aK);
            As[aK + 0][r] = av.x; As[aK + 1][r] = av.y;
            As[aK + 2][r] = av.z; As[aK + 3][r] = av.w;
        }
#pragma unroll
        for (int hh = 0; hh < 2; hh++) {
            int kk = bK + hh * 8;
            float4 bv = *(const float4*)(Bptr + (size_t)(k0 + kk) * ldb + bN);
            *(float4*)&Bs[kk][bN] = bv;
        }
        __syncthreads();
#pragma unroll
        for (int kk = 0; kk < 16; kk++) {
            unsigned long long a2[4];
#pragma unroll
            for (int p = 0; p < 4; p++)
                a2[p] = *(const unsigned long long*)&As[kk][ty * 8 + p * 2];
            float4 b0 = *(const float4*)&Bs[kk][tx * 8];
            float4 b1 = *(const float4*)&Bs[kk][tx * 8 + 4];
            unsigned long long b2[8];
            b2[0] = pk2(b0.x, b0.x); b2[1] = pk2(b0.y, b0.y);
            b2[2] = pk2(b0.z, b0.z); b2[3] = pk2(b0.w, b0.w);
            b2[4] = pk2(b1.x, b1.x); b2[5] = pk2(b1.y, b1.y);
            b2[6] = pk2(b1.z, b1.z); b2[7] = pk2(b1.w, b1.w);
#pragma unroll
            for (int p = 0; p < 4; p++)
#pragma unroll
                for (int j = 0; j < 8; j++)
                    acc[p][j] = fma2(a2[p], b2[j], acc[p][j]);
        }
        __syncthreads();
    }
}

// ---------------- QKV GEMM, scatter to [win][head][t][dh] -------------------
__global__ __launch_bounds__(256, 2)
void gemm_qkv_kernel(const float* __restrict__ h,
                     const float* __restrict__ Wq, const float* __restrict__ Wk,
                     const float* __restrict__ Wv,
                     const float* __restrict__ bq, const float* __restrict__ bk,
                     const float* __restrict__ bv,
                     float* __restrict__ q, float* __restrict__ k,
                     float* __restrict__ v) {
    const float* B; const float* bias; float* out;
    if (blockIdx.z == 0)      { B = Wq; bias = bq; out = q; }
    else if (blockIdx.z == 1) { B = Wk; bias = bk; out = k; }
    else                      { B = Wv; bias = bv; out = v; }

    unsigned long long acc[4][8];
    sgemm_core(h, B, CDIM, CDIM, blockIdx.y, blockIdx.x, acc);

    const int tx = threadIdx.x & 15, ty = threadIdx.x >> 4;
    const int c0 = blockIdx.x * 128 + tx * 8;
    const int head = c0 >> 6;
    const int dd = c0 & 63;
    float bb[8];
#pragma unroll
    for (int j = 0; j < 8; j++) bb[j] = bias[c0 + j];

#pragma unroll
    for (int p = 0; p < 4; p++) {
        float lo[8], hi[8];
#pragma unroll
        for (int j = 0; j < 8; j++) upk2(acc[p][j], lo[j], hi[j]);
        size_t r0 = (size_t)blockIdx.y * 128 + ty * 8 + 2 * p;
        {
            int win = (int)(r0 >> 8), t = (int)(r0 & 255);
            float* op = out + (size_t)win * 98304 + head * 16384 + t * 64 + dd;
            float4 o0 = make_float4(lo[0] + bb[0], lo[1] + bb[1], lo[2] + bb[2], lo[3] + bb[3]);
            float4 o1 = make_float4(lo[4] + bb[4], lo[5] + bb[5], lo[6] + bb[6], lo[7] + bb[7]);
            *(float4*)op = o0; *(float4*)(op + 4) = o1;
        }
        {
            size_t r1 = r0 + 1;
            int win = (int)(r1 >> 8), t = (int)(r1 & 255);
            float* op = out + (size_t)win * 98304 + head * 16384 + t * 64 + dd;
            float4 o0 = make_float4(hi[0] + bb[0], hi[1] + bb[1], hi[2] + bb[2], hi[3] + bb[3]);
            float4 o1 = make_float4(hi[4] + bb[4], hi[5] + bb[5], hi[6] + bb[6], hi[7] + bb[7]);
            *(float4*)op = o0; *(float4*)(op + 4) = o1;
        }
    }
}

// ---------------- GEMM + bias + residual (out = A@B + bias + res) -----------
__global__ __launch_bounds__(256, 2)
void gemm_bias_res_kernel(const float* __restrict__ A, const float* __restrict__ B,
                          const float* __restrict__ bias,
                          const float* __restrict__ res,
                          float* __restrict__ out, int K) {
    unsigned long long acc[4][8];
    sgemm_core(A, B, K, CDIM, blockIdx.y, blockIdx.x, acc);

    const int tx = threadIdx.x & 15, ty = threadIdx.x >> 4;
    const int c0 = blockIdx.x * 128 + tx * 8;
    float bb[8];
#pragma unroll
    for (int j = 0; j < 8; j++) bb[j] = bias[c0 + j];

#pragma unroll
    for (int p = 0; p < 4; p++) {
        float lo[8], hi[8];
#pragma unroll
        for (int j = 0; j < 8; j++) upk2(acc[p][j], lo[j], hi[j]);
        size_t r = (size_t)blockIdx.y * 128 + ty * 8 + 2 * p;
        const float* rp = res + r * CDIM + c0;
        float* op = out + r * CDIM + c0;
        float4 ra = *(const float4*)rp;
        float4 rb = *(const float4*)(rp + 4);
        float4 rc = *(const float4*)(rp + CDIM);
        float4 rd = *(const float4*)(rp + CDIM + 4);
        float4 oa = make_float4(lo[0] + bb[0] + ra.x, lo[1] + bb[1] + ra.y,
                                lo[2] + bb[2] + ra.z, lo[3] + bb[3] + ra.w);
        float4 ob = make_float4(lo[4] + bb[4] + rb.x, lo[5] + bb[5] + rb.y,
                                lo[6] + bb[6] + rb.z, lo[7] + bb[7] + rb.w);
        float4 oc = make_float4(hi[0] + bb[0] + rc.x, hi[1] + bb[1] + rc.y,
                                hi[2] + bb[2] + rc.z, hi[3] + bb[3] + rc.w);
        float4 od = make_float4(hi[4] + bb[4] + rd.x, hi[5] + bb[5] + rd.y,
                                hi[6] + bb[6] + rd.z, hi[7] + bb[7] + rd.w);
        *(float4*)op = oa;
        *(float4*)(op + 4) = ob;
        *(float4*)(op + CDIM) = oc;
        *(float4*)(op + CDIM + 4) = od;
    }
}

// ---------------- GEMM + bias + exact GELU ----------------------------------
__device__ __forceinline__ float gelu_f(float v) {
    return 0.5f * v * (1.0f + erff(v * 0.70710678118654752440f));
}

__global__ __launch_bounds__(256, 2)
void gemm_gelu_kernel(const float* __restrict__ A, const float* __restrict__ B,
                      const float* __restrict__ bias, float* __restrict__ out) {
    unsigned long long acc[4][8];
    sgemm_core(A, B, CDIM, MLPD, blockIdx.y, blockIdx.x, acc);

    const int tx = threadIdx.x & 15, ty = threadIdx.x >> 4;
    const int c0 = blockIdx.x * 128 + tx * 8;
    float bb[8];
#pragma unroll
    for (int j = 0; j < 8; j++) bb[j] = bias[c0 + j];

#pragma unroll
    for (int p = 0; p < 4; p++) {
        float lo[8], hi[8];
#pragma unroll
        for (int j = 0; j < 8; j++) upk2(acc[p][j], lo[j], hi[j]);
        size_t r = (size_t)blockIdx.y * 128 + ty * 8 + 2 * p;
        float* op = out + r * MLPD + c0;
        float4 oa = make_float4(gelu_f(lo[0] + bb[0]), gelu_f(lo[1] + bb[1]),
                                gelu_f(lo[2] + bb[2]), gelu_f(lo[3] + bb[3]));
        float4 ob = make_float4(gelu_f(lo[4] + bb[4]), gelu_f(lo[5] + bb[5]),
                                gelu_f(lo[6] + bb[6]), gelu_f(lo[7] + bb[7]));
        float4 oc = make_float4(gelu_f(hi[0] + bb[0]), gelu_f(hi[1] + bb[1]),
                                gelu_f(hi[2] + bb[2]), gelu_f(hi[3] + bb[3]));
        float4 od = make_float4(gelu_f(hi[4] + bb[4]), gelu_f(hi[5] + bb[5]),
                                gelu_f(hi[6] + bb[6]), gelu_f(hi[7] + bb[7]));
        *(float4*)op = oa;
        *(float4*)(op + 4) = ob;
        *(float4*)(op + MLPD) = oc;
        *(float4*)(op + MLPD + 4) = od;
    }
}

// ---------------- attention: one block per (window, head) -------------------
// T=256 tokens, dh=64. K,V in smem (128KB), q + acc packed in registers.
__global__ __launch_bounds__(256, 1)
void attn_kernel(const float* __restrict__ q, const float* __restrict__ k,
                 const float* __restrict__ v, float* __restrict__ out) {
    extern __shared__ float sm[];
    float* Ks = sm;
    float* Vs = sm + 16384;
    const int wh = blockIdx.x;       // win*6 + head
    const int t = threadIdx.x;       // query row
    const size_t base = (size_t)wh * 16384;

    {
        const float4* K4g = (const float4*)(k + base);
        const float4* V4g = (const float4*)(v + base);
        float4* K4s = (float4*)Ks;
        float4* V4s = (float4*)Vs;
#pragma unroll
        for (int i = 0; i < 16; i++) {
            K4s[i * 256 + t] = K4g[i * 256 + t];
            V4s[i * 256 + t] = V4g[i * 256 + t];
        }
    }

    // q row, pre-scaled by 1/sqrt(64)
    unsigned long long q2[32];
    {
        const float4* Q4 = (const float4*)(q + base + t * 64);
#pragma unroll
        for (int i = 0; i < 16; i++) {
            float4 qv = Q4[i];
            q2[2 * i]     = pk2(qv.x * 0.125f, qv.y * 0.125f);
            q2[2 * i + 1] = pk2(qv.z * 0.125f, qv.w * 0.125f);
        }
    }
    __syncthreads();

    unsigned long long acc2[32];
#pragma unroll
    for (int i = 0; i < 32; i++) acc2[i] = 0ULL;
    float m = -1e30f, l = 0.f;

    for (int j = 0; j < 256; j++) {
        const ulonglong2* Kr = (const ulonglong2*)(Ks + j * 64);
        unsigned long long s2[8] = {0, 0, 0, 0, 0, 0, 0, 0};
#pragma unroll
        for (int i = 0; i < 16; i++) {
            ulonglong2 kk = Kr[i];
            s2[(2 * i) & 7]     = fma2(q2[2 * i],     kk.x, s2[(2 * i) & 7]);
            s2[(2 * i + 1) & 7] = fma2(q2[2 * i + 1], kk.y, s2[(2 * i + 1) & 7]);
        }
        unsigned long long r0 = add2(add2(s2[0], s2[4]), add2(s2[1], s2[5]));
        unsigned long long r1 = add2(add2(s2[2], s2[6]), add2(s2[3], s2[7]));
        r0 = add2(r0, r1);
        float slo, shi;
        upk2(r0, slo, shi);
        float s = slo + shi;

        if (s > m) {
            float al = __expf(m - s);
            unsigned long long al2 = pk2(al, al);
            l *= al;
#pragma unroll
            for (int i = 0; i < 32; i++) acc2[i] = mul2(acc2[i], al2);
            m = s;
        }
        float p = __expf(s - m);
        l += p;
        unsigned long long p2 = pk2(p, p);
        const ulonglong2* Vr = (const ulonglong2*)(Vs + j * 64);
#pragma unroll
        for (int i = 0; i < 16; i++) {
            ulonglong2 vv = Vr[i];
            acc2[2 * i]     = fma2(p2, vv.x, acc2[2 * i]);
            acc2[2 * i + 1] = fma2(p2, vv.y, acc2[2 * i + 1]);
        }
    }

    const int win = wh / 6, head = wh % 6;
    float inv = 1.0f / l;
    float* op = out + ((size_t)win * 256 + t) * CDIM + head * 64;
#pragma unroll
    for (int i = 0; i < 16; i++) {
        float a, b, c, d;
        upk2(acc2[2 * i], a, b);
        upk2(acc2[2 * i + 1], c, d);
        float4 o = make_float4(a * inv, b * inv, c * inv, d * inv);
        *(float4*)(op + i * 4) = o;
    }
}

// ---------------------------------------------------------------------------
extern "C" void kernel_launch(void* const* d_in, const int* in_sizes, int n_in,
                              void* d_out, int out_size) {
    (void)in_sizes; (void)n_in; (void)out_size;
    const float* x   = (const float*)d_in[0];
    const float* Wq  = (const float*)d_in[1];
    const float* bq  = (const float*)d_in[2];
    const float* Wk  = (const float*)d_in[3];
    const float* bk  = (const float*)d_in[4];
    const float* Wv  = (const float*)d_in[5];
    const float* bv  = (const float*)d_in[6];
    const float* Wo  = (const float*)d_in[7];
    const float* bo  = (const float*)d_in[8];
    const float* g1  = (const float*)d_in[9];
    const float* be1 = (const float*)d_in[10];
    const float* g2  = (const float*)d_in[11];
    const float* be2 = (const float*)d_in[12];
    const float* W1  = (const float*)d_in[13];
    const float* B1  = (const float*)d_in[14];
    const float* W2  = (const float*)d_in[15];
    const float* B2  = (const float*)d_in[16];
    float* out = (float*)d_out;

    float *xw, *hb, *qb, *kb, *vb, *att, *x2, *mlp;
    cudaGetSymbolAddress((void**)&xw,  g_xw);
    cudaGetSymbolAddress((void**)&hb,  g_h);
    cudaGetSymbolAddress((void**)&qb,  g_q);
    cudaGetSymbolAddress((void**)&kb,  g_k);
    cudaGetSymbolAddress((void**)&vb,  g_v);
    cudaGetSymbolAddress((void**)&att, g_att);
    cudaGetSymbolAddress((void**)&x2,  g_x2);
    cudaGetSymbolAddress((void**)&mlp, g_mlp);

    cudaFuncSetAttribute(attn_kernel,
                         cudaFuncAttributeMaxDynamicSharedMemorySize, 131072);

    // 1) shift + window partition
    window_gather_kernel<<<dim3(12, 64, 16), 256>>>(x, xw);
    // 2) LN1
    ln_kernel<<<8192, 256>>>(xw, g1, be1, hb);
    // 3) QKV projections
    gemm_qkv_kernel<<<dim3(3, 512, 3), 256>>>(hb, Wq, Wk, Wv, bq, bk, bv,
                                              qb, kb, vb);
    // 4) windowed attention
    attn_kernel<<<1536, 256, 131072>>>(qb, kb, vb, att);
    // 5) output projection + residual
    gemm_bias_res_kernel<<<dim3(3, 512), 256>>>(att, Wo, bo, xw, x2, CDIM);
    // 6) LN2
    ln_kernel<<<8192, 256>>>(x2, g2, be2, hb);
    // 7) MLP up + GELU
    gemm_gelu_kernel<<<dim3(12, 512), 256>>>(hb, W1, B1, mlp);
    // 8) MLP down + residual  (reuse qb as y)
    gemm_bias_res_kernel<<<dim3(3, 512), 256>>>(mlp, W2, B2, x2, qb, MLPD);
    // 9) reverse window partition + shift
    window_scatter_kernel<<<dim3(12, 64, 16), 256>>>(qb, out);
}

// round 5
// speedup vs baseline: 2.1756x; 2.1756x over previous
#include <cuda_runtime.h>
#include <math.h>
#include <stdint.h>

// ---------------------------------------------------------------------------
// SwinBlock3D: GEMMs via mma.sync TF32 (HMMA tensor pipe, legal on sm_103),
// attention in packed f32x2. x(1,384,16,64,64), GRID=(4,8,8), SHIFT=(2,4,4).
// ---------------------------------------------------------------------------

#define NTOK 65536
#define CDIM 384
#define MLPD 1536

__device__ float g_xw [(size_t)NTOK * CDIM];
__device__ float g_h  [(size_t)NTOK * CDIM];
__device__ float g_q  [(size_t)NTOK * CDIM];
__device__ float g_k  [(size_t)NTOK * CDIM];
__device__ float g_v  [(size_t)NTOK * CDIM];
__device__ float g_att[(size_t)NTOK * CDIM];
__device__ float g_x2 [(size_t)NTOK * CDIM];
__device__ float g_mlp[(size_t)NTOK * MLPD];
// transposed (K-major) weights: qkv(3x147456) | o | w1 | w2
__device__ float g_wt [1769472];

// ---------------- helpers ----------------------------------------------------
__device__ __forceinline__ float tf32r(float x) {
    uint32_t u;
    asm("cvt.rna.tf32.f32 %0, %1;" : "=r"(u) : "f"(x));
    return __uint_as_float(u);
}
__device__ __forceinline__ uint32_t smem_u32(const void* p) {
    uint32_t a;
    asm("{ .reg .u64 t; cvta.to.shared.u64 t, %1; cvt.u32.u64 %0, t; }"
        : "=r"(a) : "l"(p));
    return a;
}
__device__ __forceinline__ void cp_async16(uint32_t s, const void* g) {
    asm volatile("cp.async.cg.shared.global [%0], [%1], 16;" :: "r"(s), "l"(g));
}
__device__ __forceinline__ void cp_commit() {
    asm volatile("cp.async.commit_group;");
}
template<int N> __device__ __forceinline__ void cp_wait() {
    asm volatile("cp.async.wait_group %0;" :: "n"(N));
}

// packed f32x2 (attention)
__device__ __forceinline__ unsigned long long pk2(float lo, float hi) {
    unsigned long long r;
    unsigned int a = __float_as_uint(lo), b = __float_as_uint(hi);
    asm("mov.b64 %0, {%1, %2};" : "=l"(r) : "r"(a), "r"(b));
    return r;
}
__device__ __forceinline__ void upk2(unsigned long long p, float &lo, float &hi) {
    unsigned int a, b;
    asm("mov.b64 {%0, %1}, %2;" : "=r"(a), "=r"(b) : "l"(p));
    lo = __uint_as_float(a); hi = __uint_as_float(b);
}
__device__ __forceinline__ unsigned long long fma2(unsigned long long a,
                                                   unsigned long long b,
                                                   unsigned long long c) {
    unsigned long long d;
    asm("fma.rn.f32x2 %0, %1, %2, %3;" : "=l"(d) : "l"(a), "l"(b), "l"(c));
    return d;
}
__device__ __forceinline__ unsigned long long add2(unsigned long long a,
                                                   unsigned long long b) {
    unsigned long long d;
    asm("add.rn.f32x2 %0, %1, %2;" : "=l"(d) : "l"(a), "l"(b));
    return d;
}
__device__ __forceinline__ unsigned long long mul2(unsigned long long a,
                                                   unsigned long long b) {
    unsigned long long d;
    asm("mul.rn.f32x2 %0, %1, %2;" : "=l"(d) : "l"(a), "l"(b));
    return d;
}

// ---------------- weight transpose (+ tf32 rounding) -------------------------
__global__ void transpose_kernel(const float* __restrict__ src,
                                 float* __restrict__ dst, int K, int N) {
    __shared__ float tile[32][33];
    int n0 = blockIdx.x * 32, k0 = blockIdx.y * 32;
    int tx = threadIdx.x & 31, ty = threadIdx.x >> 5;
#pragma unroll
    for (int i = ty; i < 32; i += 8)
        tile[i][tx] = src[(size_t)(k0 + i) * N + n0 + tx];
    __syncthreads();
#pragma unroll
    for (int i = ty; i < 32; i += 8)
        dst[(size_t)(n0 + i) * K + k0 + tx] = tf32r(tile[tx][i]);
}

// ---------------- shift + window partition -----------------------------------
__device__ __forceinline__ int token_index(int d, int h, int w) {
    int win = ((d >> 2) * 8 + (h >> 3)) * 8 + (w >> 3);
    int tok = ((d & 3) << 6) + ((h & 7) << 3) + (w & 7);
    return (win << 8) + tok;
}

__global__ void window_gather_kernel(const float* __restrict__ x,
                                     float* __restrict__ xw) {
    __shared__ float sm[32][65];
    const int c0 = blockIdx.x * 32;
    const int h0 = blockIdx.y;
    const int d0 = blockIdx.z;
    const int tid = threadIdx.x;
    {
        int cl = tid >> 4;
        int v4 = (tid & 15) * 4;
        const float* xp = x + (size_t)(c0 + cl) * 65536 + d0 * 4096 + h0 * 64 + v4;
        float4 a = *(const float4*)xp;
        sm[cl][v4 + 0] = a.x; sm[cl][v4 + 1] = a.y;
        sm[cl][v4 + 2] = a.z; sm[cl][v4 + 3] = a.w;
        float4 b = *(const float4*)(xp + (size_t)16 * 65536);
        sm[cl + 16][v4 + 0] = b.x; sm[cl + 16][v4 + 1] = b.y;
        sm[cl + 16][v4 + 2] = b.z; sm[cl + 16][v4 + 3] = b.w;
    }
    __syncthreads();
    int w0 = tid >> 2;
    int cg = (tid & 3) * 8;
    int d = (d0 + 14) & 15;
    int h = (h0 + 60) & 63;
    int w = (w0 + 60) & 63;
    int n = token_index(d, h, w);
    float* op = xw + (size_t)n * CDIM + c0 + cg;
    float4 o0, o1;
    o0.x = sm[cg + 0][w0]; o0.y = sm[cg + 1][w0];
    o0.z = sm[cg + 2][w0]; o0.w = sm[cg + 3][w0];
    o1.x = sm[cg + 4][w0]; o1.y = sm[cg + 5][w0];
    o1.z = sm[cg + 6][w0]; o1.w = sm[cg + 7][w0];
    *(float4*)op = o0;
    *(float4*)(op + 4) = o1;
}

__global__ void window_scatter_kernel(const float* __restrict__ y,
                                      float* __restrict__ out) {
    __shared__ float sm[32][65];
    const int c0 = blockIdx.x * 32;
    const int h0 = blockIdx.y;
    const int d0 = blockIdx.z;
    const int tid = threadIdx.x;
    {
        int w0 = tid >> 2;
        int cg = (tid & 3) * 8;
        int d = (d0 + 14) & 15;
        int h = (h0 + 60) & 63;
        int w = (w0 + 60) & 63;
        int n = token_index(d, h, w);
        const float* ip = y + (size_t)n * CDIM + c0 + cg;
        float4 a = *(const float4*)ip;
        float4 b = *(const float4*)(ip + 4);
        sm[cg + 0][w0] = a.x; sm[cg + 1][w0] = a.y;
        sm[cg + 2][w0] = a.z; sm[cg + 3][w0] = a.w;
        sm[cg + 4][w0] = b.x; sm[cg + 5][w0] = b.y;
        sm[cg + 6][w0] = b.z; sm[cg + 7][w0] = b.w;
    }
    __syncthreads();
    int cl = tid >> 4;
    int v4 = (tid & 15) * 4;
    float* op = out + (size_t)(c0 + cl) * 65536 + d0 * 4096 + h0 * 64 + v4;
    float4 o;
    o.x = sm[cl][v4 + 0]; o.y = sm[cl][v4 + 1];
    o.z = sm[cl][v4 + 2]; o.w = sm[cl][v4 + 3];
    *(float4*)op = o;
    float4 p;
    p.x = sm[cl + 16][v4 + 0]; p.y = sm[cl + 16][v4 + 1];
    p.z = sm[cl + 16][v4 + 2]; p.w = sm[cl + 16][v4 + 3];
    *(float4*)(op + (size_t)16 * 65536) = p;
}

// ---------------- layernorm (output rounded to tf32) -------------------------
__global__ void ln_kernel(const float* __restrict__ x,
                          const float* __restrict__ gam,
                          const float* __restrict__ bet,
                          float* __restrict__ out) {
    int warp = threadIdx.x >> 5;
    int lane = threadIdx.x & 31;
    size_t n = (size_t)blockIdx.x * 8 + warp;
    const float4* xr = (const float4*)(x + n * CDIM);
    float4 v[3];
    float s = 0.f, ss = 0.f;
#pragma unroll
    for (int i = 0; i < 3; i++) {
        v[i] = xr[i * 32 + lane];
        s += v[i].x + v[i].y + v[i].z + v[i].w;
        ss += v[i].x * v[i].x + v[i].y * v[i].y + v[i].z * v[i].z + v[i].w * v[i].w;
    }
#pragma unroll
    for (int off = 16; off; off >>= 1) {
        s  += __shfl_xor_sync(0xffffffffu, s,  off);
        ss += __shfl_xor_sync(0xffffffffu, ss, off);
    }
    float mean = s * (1.0f / CDIM);
    float var  = ss * (1.0f / CDIM) - mean * mean;
    float rstd = rsqrtf(var + 1e-5f);
    const float4* G = (const float4*)gam;
    const float4* B = (const float4*)bet;
    float4* o = (float4*)(out + n * CDIM);
#pragma unroll
    for (int i = 0; i < 3; i++) {
        float4 g = G[i * 32 + lane];
        float4 b = B[i * 32 + lane];
        float4 r;
        r.x = tf32r((v[i].x - mean) * rstd * g.x + b.x);
        r.y = tf32r((v[i].y - mean) * rstd * g.y + b.y);
        r.z = tf32r((v[i].z - mean) * rstd * g.z + b.z);
        r.w = tf32r((v[i].w - mean) * rstd * g.w + b.w);
        o[i * 32 + lane] = r;
    }
}

// ---------------- TF32 mma.sync GEMM core ------------------------------------
// acc[mt][nt][4] = A[rowBase+128, K] @ Bt[colBase+128, K]^T  (both K-major)
// 8 warps (2x4), warp tile 64x32; smem rows padded to 20 floats (bank-clean).
__device__ __forceinline__ void mma_tile(const float* __restrict__ A,
                                         const float* __restrict__ Bt,
                                         int K, int rowBase, int colBase,
                                         float acc[4][4][4]) {
    __shared__ __align__(16) float sA[2][2560];   // 128 rows x 20
    __shared__ __align__(16) float sB[2][2560];
    const int tid = threadIdx.x;
    const int nk = K >> 4;
    const int wid = tid >> 5, lane = tid & 31;
    const int gid = lane >> 2, tig = lane & 3;
    const int wr = (wid >> 2) * 64, wc = (wid & 3) * 32;

#pragma unroll
    for (int mt = 0; mt < 4; mt++)
#pragma unroll
        for (int nt = 0; nt < 4; nt++)
#pragma unroll
            for (int f = 0; f < 4; f++) acc[mt][nt][f] = 0.f;

    auto stage = [&](int ks, int buf) {
        const float* Ap = A + (size_t)rowBase * K + ks * 16;
        const float* Bp = Bt + (size_t)colBase * K + ks * 16;
#pragma unroll
        for (int i = 0; i < 2; i++) {
            int id = i * 256 + tid;
            int r = id >> 2, c = id & 3;
            cp_async16(smem_u32(&sA[buf][r * 20 + c * 4]),
                       Ap + (size_t)r * K + c * 4);
            cp_async16(smem_u32(&sB[buf][r * 20 + c * 4]),
                       Bp + (size_t)r * K + c * 4);
        }
        cp_commit();
    };

    stage(0, 0);
    for (int k = 0; k < nk; k++) {
        int cur = k & 1;
        if (k + 1 < nk) { stage(k + 1, cur ^ 1); cp_wait<1>(); }
        else            { cp_wait<0>(); }
        __syncthreads();
        const float* a_s = sA[cur];
        const float* b_s = sB[cur];
#pragma unroll
        for (int ks = 0; ks < 2; ks++) {
            uint32_t af[4][4], bf[4][2];
#pragma unroll
            for (int mt = 0; mt < 4; mt++) {
                const float* p = a_s + (wr + mt * 16 + gid) * 20 + ks * 8 + tig;
                af[mt][0] = __float_as_uint(p[0]);
                af[mt][1] = __float_as_uint(p[160]);
                af[mt][2] = __float_as_uint(p[4]);
                af[mt][3] = __float_as_uint(p[164]);
            }
#pragma unroll
            for (int nt = 0; nt < 4; nt++) {
                const float* p = b_s + (wc + nt * 8 + gid) * 20 + ks * 8 + tig;
                bf[nt][0] = __float_as_uint(p[0]);
                bf[nt][1] = __float_as_uint(p[4]);
            }
#pragma unroll
            for (int mt = 0; mt < 4; mt++)
#pragma unroll
                for (int nt = 0; nt < 4; nt++)
                    asm volatile(
                        "mma.sync.aligned.m16n8k8.row.col.f32.tf32.tf32.f32 "
                        "{%0,%1,%2,%3}, {%4,%5,%6,%7}, {%8,%9}, {%0,%1,%2,%3};"
                        : "+f"(acc[mt][nt][0]), "+f"(acc[mt][nt][1]),
                          "+f"(acc[mt][nt][2]), "+f"(acc[mt][nt][3])
                        : "r"(af[mt][0]), "r"(af[mt][1]),
                          "r"(af[mt][2]), "r"(af[mt][3]),
                          "r"(bf[nt][0]), "r"(bf[nt][1]));
        }
        __syncthreads();
    }
}

// ---- QKV GEMM: scatter to [win][head][t][64] --------------------------------
__global__ __launch_bounds__(256, 2)
void mm_qkv(const float* __restrict__ hb, const float* __restrict__ wt,
            const float* __restrict__ bq, const float* __restrict__ bk,
            const float* __restrict__ bv,
            float* __restrict__ q, float* __restrict__ k,
            float* __restrict__ v) {
    int g = blockIdx.z;
    const float* Bt = wt + (size_t)g * 147456;
    const float* bias = (g == 0) ? bq : (g == 1) ? bk : bv;
    float* out = (g == 0) ? q : (g == 1) ? k : v;
    int rowBase = blockIdx.y * 128, colBase = blockIdx.x * 128;

    float acc[4][4][4];
    mma_tile(hb, Bt, CDIM, rowBase, colBase, acc);

    const int lane = threadIdx.x & 31, wid = threadIdx.x >> 5;
    const int gid = lane >> 2, tig = lane & 3;
    const int wr = (wid >> 2) * 64, wc = (wid & 3) * 32;
#pragma unroll
    for (int mt = 0; mt < 4; mt++) {
        int r0 = rowBase + wr + mt * 16 + gid;
#pragma unroll
        for (int nt = 0; nt < 4; nt++) {
            int c = colBase + wc + nt * 8 + 2 * tig;
            int head = c >> 6, dd = c & 63;
            float bx = bias[c], by = bias[c + 1];
#pragma unroll
            for (int hh = 0; hh < 2; hh++) {
                int r = r0 + hh * 8;
                int win = r >> 8, t = r & 255;
                float2 o = make_float2(acc[mt][nt][2 * hh] + bx,
                                       acc[mt][nt][2 * hh + 1] + by);
                *(float2*)(out + (size_t)win * 98304 + head * 16384 +
                           t * 64 + dd) = o;
            }
        }
    }
}

// ---- GEMM + bias + residual (N=384) ----------------------------------------
__global__ __launch_bounds__(256, 2)
void mm_biasres(const float* __restrict__ A, const float* __restrict__ Bt,
                const float* __restrict__ bias, const float* __restrict__ res,
                float* __restrict__ out, int K) {
    int rowBase = blockIdx.y * 128, colBase = blockIdx.x * 128;
    float acc[4][4][4];
    mma_tile(A, Bt, K, rowBase, colBase, acc);

    const int lane = threadIdx.x & 31, wid = threadIdx.x >> 5;
    const int gid = lane >> 2, tig = lane & 3;
    const int wr = (wid >> 2) * 64, wc = (wid & 3) * 32;
#pragma unroll
    for (int mt = 0; mt < 4; mt++) {
        int r0 = rowBase + wr + mt * 16 + gid;
#pragma unroll
        for (int nt = 0; nt < 4; nt++) {
            int c = colBase + wc + nt * 8 + 2 * tig;
            float bx = bias[c], by = bias[c + 1];
#pragma unroll
            for (int hh = 0; hh < 2; hh++) {
                size_t off = (size_t)(r0 + hh * 8) * CDIM + c;
                float2 rr = *(const float2*)(res + off);
                float2 o = make_float2(acc[mt][nt][2 * hh] + bx + rr.x,
                                       acc[mt][nt][2 * hh + 1] + by + rr.y);
                *(float2*)(out + off) = o;
            }
        }
    }
}

// ---- GEMM + bias + exact GELU (N=1536, tf32-rounded out) --------------------
__device__ __forceinline__ float gelu_f(float v) {
    return 0.5f * v * (1.0f + erff(v * 0.70710678118654752440f));
}

__global__ __launch_bounds__(256, 2)
void mm_gelu(const float* __restrict__ A, const float* __restrict__ Bt,
             const float* __restrict__ bias, float* __restrict__ out) {
    int rowBase = blockIdx.y * 128, colBase = blockIdx.x * 128;
    float acc[4][4][4];
    mma_tile(A, Bt, CDIM, rowBase, colBase, acc);

    const int lane = threadIdx.x & 31, wid = threadIdx.x >> 5;
    const int gid = lane >> 2, tig = lane & 3;
    const int wr = (wid >> 2) * 64, wc = (wid & 3) * 32;
#pragma unroll
    for (int mt = 0; mt < 4; mt++) {
        int r0 = rowBase + wr + mt * 16 + gid;
#pragma unroll
        for (int nt = 0; nt < 4; nt++) {
            int c = colBase + wc + nt * 8 + 2 * tig;
            float bx = bias[c], by = bias[c + 1];
#pragma unroll
            for (int hh = 0; hh < 2; hh++) {
                size_t off = (size_t)(r0 + hh * 8) * MLPD + c;
                float2 o = make_float2(
                    tf32r(gelu_f(acc[mt][nt][2 * hh] + bx)),
                    tf32r(gelu_f(acc[mt][nt][2 * hh + 1] + by)));
                *(float2*)(out + off) = o;
            }
        }
    }
}

// ---------------- attention (f32x2, out rounded to tf32) ---------------------
__global__ __launch_bounds__(256, 1)
void attn_kernel(const float* __restrict__ q, const float* __restrict__ k,
                 const float* __restrict__ v, float* __restrict__ out) {
    extern __shared__ float sm[];
    float* Ks = sm;
    float* Vs = sm + 16384;
    const int wh = blockIdx.x;
    const int t = threadIdx.x;
    const size_t base = (size_t)wh * 16384;

    {
        const float4* K4g = (const float4*)(k + base);
        const float4* V4g = (const float4*)(v + base);
        float4* K4s = (float4*)Ks;
        float4* V4s = (float4*)Vs;
#pragma unroll
        for (int i = 0; i < 16; i++) {
            K4s[i * 256 + t] = K4g[i * 256 + t];
            V4s[i * 256 + t] = V4g[i * 256 + t];
        }
    }

    unsigned long long q2[32];
    {
        const float4* Q4 = (const float4*)(q + base + t * 64);
#pragma unroll
        for (int i = 0; i < 16; i++) {
            float4 qv = Q4[i];
            q2[2 * i]     = pk2(qv.x * 0.125f, qv.y * 0.125f);
            q2[2 * i + 1] = pk2(qv.z * 0.125f, qv.w * 0.125f);
        }
    }
    __syncthreads();

    unsigned long long acc2[32];
#pragma unroll
    for (int i = 0; i < 32; i++) acc2[i] = 0ULL;
    float m = -1e30f, l = 0.f;

    for (int j = 0; j < 256; j++) {
        const ulonglong2* Kr = (const ulonglong2*)(Ks + j * 64);
        unsigned long long s2[8] = {0, 0, 0, 0, 0, 0, 0, 0};
#pragma unroll
        for (int i = 0; i < 16; i++) {
            ulonglong2 kk = Kr[i];
            s2[(2 * i) & 7]     = fma2(q2[2 * i],     kk.x, s2[(2 * i) & 7]);
            s2[(2 * i + 1) & 7] = fma2(q2[2 * i + 1], kk.y, s2[(2 * i + 1) & 7]);
        }
        unsigned long long r0 = add2(add2(s2[0], s2[4]), add2(s2[1], s2[5]));
        unsigned long long r1 = add2(add2(s2[2], s2[6]), add2(s2[3], s2[7]));
        r0 = add2(r0, r1);
        float slo, shi;
        upk2(r0, slo, shi);
        float s = slo + shi;

        if (s > m) {
            float al = __expf(m - s);
            unsigned long long al2 = pk2(al, al);
            l *= al;
#pragma unroll
            for (int i = 0; i < 32; i++) acc2[i] = mul2(acc2[i], al2);
            m = s;
        }
        float p = __expf(s - m);
        l += p;
        unsigned long long p2 = pk2(p, p);
        const ulonglong2* Vr = (const ulonglong2*)(Vs + j * 64);
#pragma unroll
        for (int i = 0; i < 16; i++) {
            ulonglong2 vv = Vr[i];
            acc2[2 * i]     = fma2(p2, vv.x, acc2[2 * i]);
            acc2[2 * i + 1] = fma2(p2, vv.y, acc2[2 * i + 1]);
        }
    }

    const int win = wh / 6, head = wh % 6;
    float inv = 1.0f / l;
    float* op = out + ((size_t)win * 256 + t) * CDIM + head * 64;
#pragma unroll
    for (int i = 0; i < 16; i++) {
        float a, b, c, d;
        upk2(acc2[2 * i], a, b);
        upk2(acc2[2 * i + 1], c, d);
        float4 o = make_float4(tf32r(a * inv), tf32r(b * inv),
                               tf32r(c * inv), tf32r(d * inv));
        *(float4*)(op + i * 4) = o;
    }
}

// ---------------------------------------------------------------------------
extern "C" void kernel_launch(void* const* d_in, const int* in_sizes, int n_in,
                              void* d_out, int out_size) {
    (void)in_sizes; (void)n_in; (void)out_size;
    const float* x   = (const float*)d_in[0];
    const float* Wq  = (const float*)d_in[1];
    const float* bq  = (const float*)d_in[2];
    const float* Wk  = (const float*)d_in[3];
    const float* bk  = (const float*)d_in[4];
    const float* Wv  = (const float*)d_in[5];
    const float* bv  = (const float*)d_in[6];
    const float* Wo  = (const float*)d_in[7];
    const float* bo  = (const float*)d_in[8];
    const float* g1  = (const float*)d_in[9];
    const float* be1 = (const float*)d_in[10];
    const float* g2  = (const float*)d_in[11];
    const float* be2 = (const float*)d_in[12];
    const float* W1  = (const float*)d_in[13];
    const float* B1  = (const float*)d_in[14];
    const float* W2  = (const float*)d_in[15];
    const float* B2  = (const float*)d_in[16];
    float* out = (float*)d_out;

    float *xw, *hb, *qb, *kb, *vb, *att, *x2, *mlp, *wt;
    cudaGetSymbolAddress((void**)&xw,  g_xw);
    cudaGetSymbolAddress((void**)&hb,  g_h);
    cudaGetSymbolAddress((void**)&qb,  g_q);
    cudaGetSymbolAddress((void**)&kb,  g_k);
    cudaGetSymbolAddress((void**)&vb,  g_v);
    cudaGetSymbolAddress((void**)&att, g_att);
    cudaGetSymbolAddress((void**)&x2,  g_x2);
    cudaGetSymbolAddress((void**)&mlp, g_mlp);
    cudaGetSymbolAddress((void**)&wt,  g_wt);

    cudaFuncSetAttribute(attn_kernel,
                         cudaFuncAttributeMaxDynamicSharedMemorySize, 131072);

    // 0) weight transposes to K-major (+ tf32 rounding)
    transpose_kernel<<<dim3(12, 12), 256>>>(Wq, wt + 0,       CDIM, CDIM);
    transpose_kernel<<<dim3(12, 12), 256>>>(Wk, wt + 147456,  CDIM, CDIM);
    transpose_kernel<<<dim3(12, 12), 256>>>(Wv, wt + 294912,  CDIM, CDIM);
    transpose_kernel<<<dim3(12, 12), 256>>>(Wo, wt + 442368,  CDIM, CDIM);
    transpose_kernel<<<dim3(48, 12), 256>>>(W1, wt + 589824,  CDIM, MLPD);
    transpose_kernel<<<dim3(12, 48), 256>>>(W2, wt + 1179648, MLPD, CDIM);

    // 1) shift + window partition
    window_gather_kernel<<<dim3(12, 64, 16), 256>>>(x, xw);
    // 2) LN1 (tf32-rounded)
    ln_kernel<<<8192, 256>>>(xw, g1, be1, hb);
    // 3) QKV projections (mma.sync tf32)
    mm_qkv<<<dim3(3, 512, 3), 256>>>(hb, wt, bq, bk, bv, qb, kb, vb);
    // 4) windowed attention
    attn_kernel<<<1536, 256, 131072>>>(qb, kb, vb, att);
    // 5) output projection + residual
    mm_biasres<<<dim3(3, 512), 256>>>(att, wt + 442368, bo, xw, x2, CDIM);
    // 6) LN2 (tf32-rounded)
    ln_kernel<<<8192, 256>>>(x2, g2, be2, hb);
    // 7) MLP up + GELU (tf32-rounded out)
    mm_gelu<<<dim3(12, 512), 256>>>(hb, wt + 589824, B1, mlp);
    // 8) MLP down + residual
    mm_biasres<<<dim3(3, 512), 256>>>(mlp, wt + 1179648, B2, x2, qb, MLPD);
    // 9) reverse window partition + shift
    window_scatter_kernel<<<dim3(12, 64, 16), 256>>>(qb, out);
}

// round 6
// speedup vs baseline: 2.6690x; 1.2268x over previous
#include <cuda_runtime.h>
#include <math.h>
#include <stdint.h>

// ---------------------------------------------------------------------------
// SwinBlock3D: GEMMs + attention via mma.sync TF32 (HMMA tensor pipe).
// x(1,384,16,64,64)  GRID=(4,8,8) SHIFT=(2,4,4) HEADS=6 dh=64 MLP=1536
// ---------------------------------------------------------------------------

#define NTOK 65536
#define CDIM 384
#define MLPD 1536

__device__ float g_xw [(size_t)NTOK * CDIM];
__device__ float g_h  [(size_t)NTOK * CDIM];
__device__ float g_q  [(size_t)NTOK * CDIM];
__device__ float g_k  [(size_t)NTOK * CDIM];
__device__ float g_v  [(size_t)NTOK * CDIM];
__device__ float g_att[(size_t)NTOK * CDIM];
__device__ float g_x2 [(size_t)NTOK * CDIM];
__device__ float g_mlp[(size_t)NTOK * MLPD];
// transposed (K-major) weights: qkv(3x147456) | o | w1 | w2
__device__ float g_wt [1769472];

// ---------------- helpers ----------------------------------------------------
__device__ __forceinline__ float tf32r(float x) {
    uint32_t u;
    asm("cvt.rna.tf32.f32 %0, %1;" : "=r"(u) : "f"(x));
    return __uint_as_float(u);
}
__device__ __forceinline__ uint32_t smem_u32(const void* p) {
    uint32_t a;
    asm("{ .reg .u64 t; cvta.to.shared.u64 t, %1; cvt.u32.u64 %0, t; }"
        : "=r"(a) : "l"(p));
    return a;
}
__device__ __forceinline__ void cp_async16(uint32_t s, const void* g) {
    asm volatile("cp.async.cg.shared.global [%0], [%1], 16;" :: "r"(s), "l"(g));
}
__device__ __forceinline__ void cp_commit() {
    asm volatile("cp.async.commit_group;");
}
template<int N> __device__ __forceinline__ void cp_wait() {
    asm volatile("cp.async.wait_group %0;" :: "n"(N));
}
__device__ __forceinline__ void mma_tf32(float c[4], const uint32_t a[4],
                                         const uint32_t b[2]) {
    asm volatile(
        "mma.sync.aligned.m16n8k8.row.col.f32.tf32.tf32.f32 "
        "{%0,%1,%2,%3}, {%4,%5,%6,%7}, {%8,%9}, {%0,%1,%2,%3};"
        : "+f"(c[0]), "+f"(c[1]), "+f"(c[2]), "+f"(c[3])
        : "r"(a[0]), "r"(a[1]), "r"(a[2]), "r"(a[3]), "r"(b[0]), "r"(b[1]));
}

// ---------------- weight transpose (+ tf32 rounding) -------------------------
__global__ void transpose_kernel(const float* __restrict__ src,
                                 float* __restrict__ dst, int K, int N) {
    __shared__ float tile[32][33];
    int n0 = blockIdx.x * 32, k0 = blockIdx.y * 32;
    int tx = threadIdx.x & 31, ty = threadIdx.x >> 5;
#pragma unroll
    for (int i = ty; i < 32; i += 8)
        tile[i][tx] = src[(size_t)(k0 + i) * N + n0 + tx];
    __syncthreads();
#pragma unroll
    for (int i = ty; i < 32; i += 8)
        dst[(size_t)(n0 + i) * K + k0 + tx] = tf32r(tile[tx][i]);
}

// ---------------- shift + window partition -----------------------------------
__device__ __forceinline__ int token_index(int d, int h, int w) {
    int win = ((d >> 2) * 8 + (h >> 3)) * 8 + (w >> 3);
    int tok = ((d & 3) << 6) + ((h & 7) << 3) + (w & 7);
    return (win << 8) + tok;
}

__global__ void window_gather_kernel(const float* __restrict__ x,
                                     float* __restrict__ xw) {
    __shared__ float sm[32][65];
    const int c0 = blockIdx.x * 32;
    const int h0 = blockIdx.y;
    const int d0 = blockIdx.z;
    const int tid = threadIdx.x;
    {
        int cl = tid >> 4;
        int v4 = (tid & 15) * 4;
        const float* xp = x + (size_t)(c0 + cl) * 65536 + d0 * 4096 + h0 * 64 + v4;
        float4 a = *(const float4*)xp;
        sm[cl][v4 + 0] = a.x; sm[cl][v4 + 1] = a.y;
        sm[cl][v4 + 2] = a.z; sm[cl][v4 + 3] = a.w;
        float4 b = *(const float4*)(xp + (size_t)16 * 65536);
        sm[cl + 16][v4 + 0] = b.x; sm[cl + 16][v4 + 1] = b.y;
        sm[cl + 16][v4 + 2] = b.z; sm[cl + 16][v4 + 3] = b.w;
    }
    __syncthreads();
    int w0 = tid >> 2;
    int cg = (tid & 3) * 8;
    int d = (d0 + 14) & 15;
    int h = (h0 + 60) & 63;
    int w = (w0 + 60) & 63;
    int n = token_index(d, h, w);
    float* op = xw + (size_t)n * CDIM + c0 + cg;
    float4 o0, o1;
    o0.x = sm[cg + 0][w0]; o0.y = sm[cg + 1][w0];
    o0.z = sm[cg + 2][w0]; o0.w = sm[cg + 3][w0];
    o1.x = sm[cg + 4][w0]; o1.y = sm[cg + 5][w0];
    o1.z = sm[cg + 6][w0]; o1.w = sm[cg + 7][w0];
    *(float4*)op = o0;
    *(float4*)(op + 4) = o1;
}

__global__ void window_scatter_kernel(const float* __restrict__ y,
                                      float* __restrict__ out) {
    __shared__ float sm[32][65];
    const int c0 = blockIdx.x * 32;
    const int h0 = blockIdx.y;
    const int d0 = blockIdx.z;
    const int tid = threadIdx.x;
    {
        int w0 = tid >> 2;
        int cg = (tid & 3) * 8;
        int d = (d0 + 14) & 15;
        int h = (h0 + 60) & 63;
        int w = (w0 + 60) & 63;
        int n = token_index(d, h, w);
        const float* ip = y + (size_t)n * CDIM + c0 + cg;
        float4 a = *(const float4*)ip;
        float4 b = *(const float4*)(ip + 4);
        sm[cg + 0][w0] = a.x; sm[cg + 1][w0] = a.y;
        sm[cg + 2][w0] = a.z; sm[cg + 3][w0] = a.w;
        sm[cg + 4][w0] = b.x; sm[cg + 5][w0] = b.y;
        sm[cg + 6][w0] = b.z; sm[cg + 7][w0] = b.w;
    }
    __syncthreads();
    int cl = tid >> 4;
    int v4 = (tid & 15) * 4;
    float* op = out + (size_t)(c0 + cl) * 65536 + d0 * 4096 + h0 * 64 + v4;
    float4 o;
    o.x = sm[cl][v4 + 0]; o.y = sm[cl][v4 + 1];
    o.z = sm[cl][v4 + 2]; o.w = sm[cl][v4 + 3];
    *(float4*)op = o;
    float4 p;
    p.x = sm[cl + 16][v4 + 0]; p.y = sm[cl + 16][v4 + 1];
    p.z = sm[cl + 16][v4 + 2]; p.w = sm[cl + 16][v4 + 3];
    *(float4*)(op + (size_t)16 * 65536) = p;
}

// ---------------- layernorm (output rounded to tf32) -------------------------
__global__ void ln_kernel(const float* __restrict__ x,
                          const float* __restrict__ gam,
                          const float* __restrict__ bet,
                          float* __restrict__ out) {
    int warp = threadIdx.x >> 5;
    int lane = threadIdx.x & 31;
    size_t n = (size_t)blockIdx.x * 8 + warp;
    const float4* xr = (const float4*)(x + n * CDIM);
    float4 v[3];
    float s = 0.f, ss = 0.f;
#pragma unroll
    for (int i = 0; i < 3; i++) {
        v[i] = xr[i * 32 + lane];
        s += v[i].x + v[i].y + v[i].z + v[i].w;
        ss += v[i].x * v[i].x + v[i].y * v[i].y + v[i].z * v[i].z + v[i].w * v[i].w;
    }
#pragma unroll
    for (int off = 16; off; off >>= 1) {
        s  += __shfl_xor_sync(0xffffffffu, s,  off);
        ss += __shfl_xor_sync(0xffffffffu, ss, off);
    }
    float mean = s * (1.0f / CDIM);
    float var  = ss * (1.0f / CDIM) - mean * mean;
    float rstd = rsqrtf(var + 1e-5f);
    const float4* G = (const float4*)gam;
    const float4* B = (const float4*)bet;
    float4* o = (float4*)(out + n * CDIM);
#pragma unroll
    for (int i = 0; i < 3; i++) {
        float4 g = G[i * 32 + lane];
        float4 b = B[i * 32 + lane];
        float4 r;
        r.x = tf32r((v[i].x - mean) * rstd * g.x + b.x);
        r.y = tf32r((v[i].y - mean) * rstd * g.y + b.y);
        r.z = tf32r((v[i].z - mean) * rstd * g.z + b.z);
        r.w = tf32r((v[i].w - mean) * rstd * g.w + b.w);
        o[i * 32 + lane] = r;
    }
}

// ---------------- TF32 mma.sync GEMM core ------------------------------------
__device__ __forceinline__ void mma_tile(const float* __restrict__ A,
                                         const float* __restrict__ Bt,
                                         int K, int rowBase, int colBase,
                                         float acc[4][4][4]) {
    __shared__ __align__(16) float sA[2][2560];   // 128 rows x 20
    __shared__ __align__(16) float sB[2][2560];
    const int tid = threadIdx.x;
    const int nk = K >> 4;
    const int wid = tid >> 5, lane = tid & 31;
    const int gid = lane >> 2, tig = lane & 3;
    const int wr = (wid >> 2) * 64, wc = (wid & 3) * 32;

#pragma unroll
    for (int mt = 0; mt < 4; mt++)
#pragma unroll
        for (int nt = 0; nt < 4; nt++)
#pragma unroll
            for (int f = 0; f < 4; f++) acc[mt][nt][f] = 0.f;

    auto stage = [&](int ks, int buf) {
        const float* Ap = A + (size_t)rowBase * K + ks * 16;
        const float* Bp = Bt + (size_t)colBase * K + ks * 16;
#pragma unroll
        for (int i = 0; i < 2; i++) {
            int id = i * 256 + tid;
            int r = id >> 2, c = id & 3;
            cp_async16(smem_u32(&sA[buf][r * 20 + c * 4]),
                       Ap + (size_t)r * K + c * 4);
            cp_async16(smem_u32(&sB[buf][r * 20 + c * 4]),
                       Bp + (size_t)r * K + c * 4);
        }
        cp_commit();
    };

    stage(0, 0);
    for (int k = 0; k < nk; k++) {
        int cur = k & 1;
        if (k + 1 < nk) { stage(k + 1, cur ^ 1); cp_wait<1>(); }
        else            { cp_wait<0>(); }
        __syncthreads();
        const float* a_s = sA[cur];
        const float* b_s = sB[cur];
#pragma unroll
        for (int ks = 0; ks < 2; ks++) {
            uint32_t af[4][4], bf[4][2];
#pragma unroll
            for (int mt = 0; mt < 4; mt++) {
                const float* p = a_s + (wr + mt * 16 + gid) * 20 + ks * 8 + tig;
                af[mt][0] = __float_as_uint(p[0]);
                af[mt][1] = __float_as_uint(p[160]);
                af[mt][2] = __float_as_uint(p[4]);
                af[mt][3] = __float_as_uint(p[164]);
            }
#pragma unroll
            for (int nt = 0; nt < 4; nt++) {
                const float* p = b_s + (wc + nt * 8 + gid) * 20 + ks * 8 + tig;
                bf[nt][0] = __float_as_uint(p[0]);
                bf[nt][1] = __float_as_uint(p[4]);
            }
#pragma unroll
            for (int mt = 0; mt < 4; mt++)
#pragma unroll
                for (int nt = 0; nt < 4; nt++)
                    mma_tf32(acc[mt][nt], af[mt], bf[nt]);
        }
        __syncthreads();
    }
}

// ---- QKV GEMM: scatter to [win][head][t][64] --------------------------------
__global__ __launch_bounds__(256, 2)
void mm_qkv(const float* __restrict__ hb, const float* __restrict__ wt,
            const float* __restrict__ bq, const float* __restrict__ bk,
            const float* __restrict__ bv,
            float* __restrict__ q, float* __restrict__ k,
            float* __restrict__ v) {
    int g = blockIdx.z;
    const float* Bt = wt + (size_t)g * 147456;
    const float* bias = (g == 0) ? bq : (g == 1) ? bk : bv;
    float* out = (g == 0) ? q : (g == 1) ? k : v;
    int rowBase = blockIdx.y * 128, colBase = blockIdx.x * 128;

    float acc[4][4][4];
    mma_tile(hb, Bt, CDIM, rowBase, colBase, acc);

    const int lane = threadIdx.x & 31, wid = threadIdx.x >> 5;
    const int gid = lane >> 2, tig = lane & 3;
    const int wr = (wid >> 2) * 64, wc = (wid & 3) * 32;
#pragma unroll
    for (int mt = 0; mt < 4; mt++) {
        int r0 = rowBase + wr + mt * 16 + gid;
#pragma unroll
        for (int nt = 0; nt < 4; nt++) {
            int c = colBase + wc + nt * 8 + 2 * tig;
            int head = c >> 6, dd = c & 63;
            float bx = bias[c], by = bias[c + 1];
#pragma unroll
            for (int hh = 0; hh < 2; hh++) {
                int r = r0 + hh * 8;
                int win = r >> 8, t = r & 255;
                float2 o = make_float2(acc[mt][nt][2 * hh] + bx,
                                       acc[mt][nt][2 * hh + 1] + by);
                *(float2*)(out + (size_t)win * 98304 + head * 16384 +
                           t * 64 + dd) = o;
            }
        }
    }
}

// ---- GEMM + bias + residual (N=384) ----------------------------------------
__global__ __launch_bounds__(256, 2)
void mm_biasres(const float* __restrict__ A, const float* __restrict__ Bt,
                const float* __restrict__ bias, const float* __restrict__ res,
                float* __restrict__ out, int K) {
    int rowBase = blockIdx.y * 128, colBase = blockIdx.x * 128;
    float acc[4][4][4];
    mma_tile(A, Bt, K, rowBase, colBase, acc);

    const int lane = threadIdx.x & 31, wid = threadIdx.x >> 5;
    const int gid = lane >> 2, tig = lane & 3;
    const int wr = (wid >> 2) * 64, wc = (wid & 3) * 32;
#pragma unroll
    for (int mt = 0; mt < 4; mt++) {
        int r0 = rowBase + wr + mt * 16 + gid;
#pragma unroll
        for (int nt = 0; nt < 4; nt++) {
            int c = colBase + wc + nt * 8 + 2 * tig;
            float bx = bias[c], by = bias[c + 1];
#pragma unroll
            for (int hh = 0; hh < 2; hh++) {
                size_t off = (size_t)(r0 + hh * 8) * CDIM + c;
                float2 rr = *(const float2*)(res + off);
                float2 o = make_float2(acc[mt][nt][2 * hh] + bx + rr.x,
                                       acc[mt][nt][2 * hh + 1] + by + rr.y);
                *(float2*)(out + off) = o;
            }
        }
    }
}

// ---- GEMM + bias + exact GELU (N=1536, tf32-rounded out) --------------------
__device__ __forceinline__ float gelu_f(float v) {
    return 0.5f * v * (1.0f + erff(v * 0.70710678118654752440f));
}

__global__ __launch_bounds__(256, 2)
void mm_gelu(const float* __restrict__ A, const float* __restrict__ Bt,
             const float* __restrict__ bias, float* __restrict__ out) {
    int rowBase = blockIdx.y * 128, colBase = blockIdx.x * 128;
    float acc[4][4][4];
    mma_tile(A, Bt, CDIM, rowBase, colBase, acc);

    const int lane = threadIdx.x & 31, wid = threadIdx.x >> 5;
    const int gid = lane >> 2, tig = lane & 3;
    const int wr = (wid >> 2) * 64, wc = (wid & 3) * 32;
#pragma unroll
    for (int mt = 0; mt < 4; mt++) {
        int r0 = rowBase + wr + mt * 16 + gid;
#pragma unroll
        for (int nt = 0; nt < 4; nt++) {
            int c = colBase + wc + nt * 8 + 2 * tig;
            float bx = bias[c], by = bias[c + 1];
#pragma unroll
            for (int hh = 0; hh < 2; hh++) {
                size_t off = (size_t)(r0 + hh * 8) * MLPD + c;
                float2 o = make_float2(
                    tf32r(gelu_f(acc[mt][nt][2 * hh] + bx)),
                    tf32r(gelu_f(acc[mt][nt][2 * hh + 1] + by)));
                *(float2*)(out + off) = o;
            }
        }
    }
}

// ---------------- attention via mma.sync TF32 --------------------------------
// One CTA per (window, head). 8 warps x 32 query rows. Flash over 4 key
// blocks of 64. smem: K[256x68] | V[256x72] | P/Q[256x68] (warp-private P).
#define KSTR 68
#define VSTR 72
#define ATT_SMEM ((256 * KSTR + 256 * VSTR + 256 * KSTR) * 4)

__global__ __launch_bounds__(256, 1)
void attn_mma(const float* __restrict__ q, const float* __restrict__ k,
              const float* __restrict__ v, float* __restrict__ out) {
    extern __shared__ float sm[];
    float* Ks = sm;
    float* Vs = sm + 256 * KSTR;
    float* Ps = Vs + 256 * VSTR;
    const int wh = blockIdx.x;
    const size_t base = (size_t)wh * 16384;
    const int tid = threadIdx.x;
    const int wid = tid >> 5, lane = tid & 31;
    const int gid = lane >> 2, tig = lane & 3;
    const int qr = wid * 32;
    float* Pw = Ps + wid * 32 * KSTR;

    // stage K, V (tf32-rounded), Q (scaled+rounded) into smem
    {
        const float4* Kg = (const float4*)(k + base + tid * 64);
        const float4* Vg = (const float4*)(v + base + tid * 64);
        const float4* Qg = (const float4*)(q + base + tid * 64);
#pragma unroll
        for (int i = 0; i < 16; i++) {
            float4 a = Kg[i];
            Ks[tid * KSTR + 4 * i + 0] = tf32r(a.x);
            Ks[tid * KSTR + 4 * i + 1] = tf32r(a.y);
            Ks[tid * KSTR + 4 * i + 2] = tf32r(a.z);
            Ks[tid * KSTR + 4 * i + 3] = tf32r(a.w);
            float4 b = Vg[i];
            Vs[tid * VSTR + 4 * i + 0] = tf32r(b.x);
            Vs[tid * VSTR + 4 * i + 1] = tf32r(b.y);
            Vs[tid * VSTR + 4 * i + 2] = tf32r(b.z);
            Vs[tid * VSTR + 4 * i + 3] = tf32r(b.w);
            float4 c = Qg[i];
            Ps[tid * KSTR + 4 * i + 0] = tf32r(c.x * 0.125f);
            Ps[tid * KSTR + 4 * i + 1] = tf32r(c.y * 0.125f);
            Ps[tid * KSTR + 4 * i + 2] = tf32r(c.z * 0.125f);
            Ps[tid * KSTR + 4 * i + 3] = tf32r(c.w * 0.125f);
        }
    }
    __syncthreads();

    // Q fragments (held in registers for the whole kernel)
    uint32_t qf[2][8][4];
#pragma unroll
    for (int mt = 0; mt < 2; mt++)
#pragma unroll
        for (int ks = 0; ks < 8; ks++) {
            const float* p = Ps + (qr + mt * 16 + gid) * KSTR + ks * 8 + tig;
            qf[mt][ks][0] = __float_as_uint(p[0]);
            qf[mt][ks][1] = __float_as_uint(p[8 * KSTR]);
            qf[mt][ks][2] = __float_as_uint(p[4]);
            qf[mt][ks][3] = __float_as_uint(p[8 * KSTR + 4]);
        }
    __syncthreads();   // Ps region now free -> P scratch

    float oacc[2][8][4];
#pragma unroll
    for (int mt = 0; mt < 2; mt++)
#pragma unroll
        for (int nt = 0; nt < 8; nt++)
#pragma unroll
            for (int f = 0; f < 4; f++) oacc[mt][nt][f] = 0.f;
    float mrow[2][2] = {{-1e30f, -1e30f}, {-1e30f, -1e30f}};
    float lrow[2][2] = {{0.f, 0.f}, {0.f, 0.f}};

    for (int jb = 0; jb < 4; jb++) {
        // ---- S = Q @ K_jb^T ----
        float sacc[2][8][4];
#pragma unroll
        for (int mt = 0; mt < 2; mt++)
#pragma unroll
            for (int nt = 0; nt < 8; nt++)
#pragma unroll
                for (int f = 0; f < 4; f++) sacc[mt][nt][f] = 0.f;
#pragma unroll
        for (int ks = 0; ks < 8; ks++) {
            uint32_t kf[8][2];
#pragma unroll
            for (int nt = 0; nt < 8; nt++) {
                const float* p = Ks + (jb * 64 + nt * 8 + gid) * KSTR + ks * 8 + tig;
                kf[nt][0] = __float_as_uint(p[0]);
                kf[nt][1] = __float_as_uint(p[4]);
            }
#pragma unroll
            for (int mt = 0; mt < 2; mt++)
#pragma unroll
                for (int nt = 0; nt < 8; nt++)
                    mma_tf32(sacc[mt][nt], qf[mt][ks], kf[nt]);
        }

        // ---- online softmax (rows: mt*16+gid (+8)) ----
        __syncwarp();   // previous PV reads of Pw done before overwrite
#pragma unroll
        for (int mt = 0; mt < 2; mt++)
#pragma unroll
            for (int hh = 0; hh < 2; hh++) {
                float bm = -1e30f;
#pragma unroll
                for (int nt = 0; nt < 8; nt++) {
                    bm = fmaxf(bm, sacc[mt][nt][2 * hh]);
                    bm = fmaxf(bm, sacc[mt][nt][2 * hh + 1]);
                }
                bm = fmaxf(bm, __shfl_xor_sync(0xffffffffu, bm, 1));
                bm = fmaxf(bm, __shfl_xor_sync(0xffffffffu, bm, 2));
                float mn = fmaxf(mrow[mt][hh], bm);
                float scale = __expf(mrow[mt][hh] - mn);
                mrow[mt][hh] = mn;
                lrow[mt][hh] *= scale;
#pragma unroll
                for (int nt = 0; nt < 8; nt++) {
                    oacc[mt][nt][2 * hh]     *= scale;
                    oacc[mt][nt][2 * hh + 1] *= scale;
                }
                float psum = 0.f;
                int row = mt * 16 + gid + hh * 8;
#pragma unroll
                for (int nt = 0; nt < 8; nt++) {
                    float p0 = tf32r(__expf(sacc[mt][nt][2 * hh]     - mn));
                    float p1 = tf32r(__expf(sacc[mt][nt][2 * hh + 1] - mn));
                    psum += p0 + p1;
                    *(float2*)(Pw + row * KSTR + nt * 8 + 2 * tig) =
                        make_float2(p0, p1);
                }
                psum += __shfl_xor_sync(0xffffffffu, psum, 1);
                psum += __shfl_xor_sync(0xffffffffu, psum, 2);
                lrow[mt][hh] += psum;
            }
        __syncwarp();

        // ---- O += P @ V_jb ----
#pragma unroll
        for (int ks = 0; ks < 8; ks++) {
            uint32_t pf[2][4], vf[8][2];
#pragma unroll
            for (int mt = 0; mt < 2; mt++) {
                const float* p = Pw + (mt * 16 + gid) * KSTR + ks * 8 + tig;
                pf[mt][0] = __float_as_uint(p[0]);
                pf[mt][1] = __float_as_uint(p[8 * KSTR]);
                pf[mt][2] = __float_as_uint(p[4]);
                pf[mt][3] = __float_as_uint(p[8 * KSTR + 4]);
            }
#pragma unroll
            for (int nt = 0; nt < 8; nt++) {
                const float* p = Vs + (jb * 64 + ks * 8 + tig) * VSTR + nt * 8 + gid;
                vf[nt][0] = __float_as_uint(p[0]);
                vf[nt][1] = __float_as_uint(p[4 * VSTR]);
            }
#pragma unroll
            for (int mt = 0; mt < 2; mt++)
#pragma unroll
                for (int nt = 0; nt < 8; nt++)
                    mma_tf32(oacc[mt][nt], pf[mt], vf[nt]);
        }
    }

    // ---- epilogue: divide by l, round to tf32, write token-major ----
    const int win = wh / 6, head = wh % 6;
#pragma unroll
    for (int mt = 0; mt < 2; mt++)
#pragma unroll
        for (int hh = 0; hh < 2; hh++) {
            float inv = 1.0f / lrow[mt][hh];
            int row = qr + mt * 16 + gid + hh * 8;
            float* op = out + ((size_t)win * 256 + row) * CDIM + head * 64;
#pragma unroll
            for (int nt = 0; nt < 8; nt++) {
                float2 o = make_float2(
                    tf32r(oacc[mt][nt][2 * hh] * inv),
                    tf32r(oacc[mt][nt][2 * hh + 1] * inv));
                *(float2*)(op + nt * 8 + 2 * tig) = o;
            }
        }
}

// ---------------------------------------------------------------------------
extern "C" void kernel_launch(void* const* d_in, const int* in_sizes, int n_in,
                              void* d_out, int out_size) {
    (void)in_sizes; (void)n_in; (void)out_size;
    const float* x   = (const float*)d_in[0];
    const float* Wq  = (const float*)d_in[1];
    const float* bq  = (const float*)d_in[2];
    const float* Wk  = (const float*)d_in[3];
    const float* bk  = (const float*)d_in[4];
    const float* Wv  = (const float*)d_in[5];
    const float* bv  = (const float*)d_in[6];
    const float* Wo  = (const float*)d_in[7];
    const float* bo  = (const float*)d_in[8];
    const float* g1  = (const float*)d_in[9];
    const float* be1 = (const float*)d_in[10];
    const float* g2  = (const float*)d_in[11];
    const float* be2 = (const float*)d_in[12];
    const float* W1  = (const float*)d_in[13];
    const float* B1  = (const float*)d_in[14];
    const float* W2  = (const float*)d_in[15];
    const float* B2  = (const float*)d_in[16];
    float* out = (float*)d_out;

    float *xw, *hb, *qb, *kb, *vb, *att, *x2, *mlp, *wt;
    cudaGetSymbolAddress((void**)&xw,  g_xw);
    cudaGetSymbolAddress((void**)&hb,  g_h);
    cudaGetSymbolAddress((void**)&qb,  g_q);
    cudaGetSymbolAddress((void**)&kb,  g_k);
    cudaGetSymbolAddress((void**)&vb,  g_v);
    cudaGetSymbolAddress((void**)&att, g_att);
    cudaGetSymbolAddress((void**)&x2,  g_x2);
    cudaGetSymbolAddress((void**)&mlp, g_mlp);
    cudaGetSymbolAddress((void**)&wt,  g_wt);

    cudaFuncSetAttribute(attn_mma,
                         cudaFuncAttributeMaxDynamicSharedMemorySize, ATT_SMEM);

    // 0) weight transposes to K-major (+ tf32 rounding)
    transpose_kernel<<<dim3(12, 12), 256>>>(Wq, wt + 0,       CDIM, CDIM);
    transpose_kernel<<<dim3(12, 12), 256>>>(Wk, wt + 147456,  CDIM, CDIM);
    transpose_kernel<<<dim3(12, 12), 256>>>(Wv, wt + 294912,  CDIM, CDIM);
    transpose_kernel<<<dim3(12, 12), 256>>>(Wo, wt + 442368,  CDIM, CDIM);
    transpose_kernel<<<dim3(48, 12), 256>>>(W1, wt + 589824,  CDIM, MLPD);
    transpose_kernel<<<dim3(12, 48), 256>>>(W2, wt + 1179648, MLPD, CDIM);

    // 1) shift + window partition
    window_gather_kernel<<<dim3(12, 64, 16), 256>>>(x, xw);
    // 2) LN1 (tf32-rounded)
    ln_kernel<<<8192, 256>>>(xw, g1, be1, hb);
    // 3) QKV projections (mma.sync tf32)
    mm_qkv<<<dim3(3, 512, 3), 256>>>(hb, wt, bq, bk, bv, qb, kb, vb);
    // 4) windowed attention (mma.sync tf32 flash)
    attn_mma<<<1536, 256, ATT_SMEM>>>(qb, kb, vb, att);
    // 5) output projection + residual
    mm_biasres<<<dim3(3, 512), 256>>>(att, wt + 442368, bo, xw, x2, CDIM);
    // 6) LN2 (tf32-rounded)
    ln_kernel<<<8192, 256>>>(x2, g2, be2, hb);
    // 7) MLP up + GELU (tf32-rounded out)
    mm_gelu<<<dim3(12, 512), 256>>>(hb, wt + 589824, B1, mlp);
    // 8) MLP down + residual
    mm_biasres<<<dim3(3, 512), 256>>>(mlp, wt + 1179648, B2, x2, qb, MLPD);
    // 9) reverse window partition + shift
    window_scatter_kernel<<<dim3(12, 64, 16), 256>>>(qb, out);
}

// round 7
// speedup vs baseline: 3.2521x; 1.2185x over previous
#include <cuda_runtime.h>
#include <cuda_bf16.h>
#include <math.h>
#include <stdint.h>

// ---------------------------------------------------------------------------
// SwinBlock3D: GEMMs via mma.sync BF16 (m16n8k16, fp32 accum), attention via
// mma.sync TF32 flash. x(1,384,16,64,64) GRID=(4,8,8) SHIFT=(2,4,4) HEADS=6.
// All GEMM A/B inputs quantized to bf16 at producer side; residual paths fp32.
// ---------------------------------------------------------------------------

#define NTOK 65536
#define CDIM 384
#define MLPD 1536

typedef __nv_bfloat16 bf16;
typedef __nv_bfloat162 bf162;

__device__ float g_xw [(size_t)NTOK * CDIM];   // fp32 residual stream
__device__ bf16  g_h  [(size_t)NTOK * CDIM];   // LN outputs (bf16 GEMM A)
__device__ float g_q  [(size_t)NTOK * CDIM];
__device__ float g_k  [(size_t)NTOK * CDIM];
__device__ float g_v  [(size_t)NTOK * CDIM];
__device__ bf16  g_att[(size_t)NTOK * CDIM];   // attention out (bf16 GEMM A)
__device__ float g_x2 [(size_t)NTOK * CDIM];   // fp32 residual stream
__device__ bf16  g_mlp[(size_t)NTOK * MLPD];   // GELU out (bf16 GEMM A)
// transposed (K-major) bf16 weights: qkv(3x147456) | o | w1 | w2
__device__ bf16  g_wt [1769472];

// ---------------- helpers ----------------------------------------------------
__device__ __forceinline__ float tf32r(float x) {
    uint32_t u;
    asm("cvt.rna.tf32.f32 %0, %1;" : "=r"(u) : "f"(x));
    return __uint_as_float(u);
}
__device__ __forceinline__ uint32_t smem_u32(const void* p) {
    uint32_t a;
    asm("{ .reg .u64 t; cvta.to.shared.u64 t, %1; cvt.u32.u64 %0, t; }"
        : "=r"(a) : "l"(p));
    return a;
}
__device__ __forceinline__ void cp_async16(uint32_t s, const void* g) {
    asm volatile("cp.async.cg.shared.global [%0], [%1], 16;" :: "r"(s), "l"(g));
}
__device__ __forceinline__ void cp_commit() {
    asm volatile("cp.async.commit_group;");
}
template<int N> __device__ __forceinline__ void cp_wait() {
    asm volatile("cp.async.wait_group %0;" :: "n"(N));
}
__device__ __forceinline__ void mma_bf16(float c[4], const uint32_t a[4],
                                         const uint32_t b[2]) {
    asm volatile(
        "mma.sync.aligned.m16n8k16.row.col.f32.bf16.bf16.f32 "
        "{%0,%1,%2,%3}, {%4,%5,%6,%7}, {%8,%9}, {%0,%1,%2,%3};"
        : "+f"(c[0]), "+f"(c[1]), "+f"(c[2]), "+f"(c[3])
        : "r"(a[0]), "r"(a[1]), "r"(a[2]), "r"(a[3]), "r"(b[0]), "r"(b[1]));
}
__device__ __forceinline__ void mma_tf32(float c[4], const uint32_t a[4],
                                         const uint32_t b[2]) {
    asm volatile(
        "mma.sync.aligned.m16n8k8.row.col.f32.tf32.tf32.f32 "
        "{%0,%1,%2,%3}, {%4,%5,%6,%7}, {%8,%9}, {%0,%1,%2,%3};"
        : "+f"(c[0]), "+f"(c[1]), "+f"(c[2]), "+f"(c[3])
        : "r"(a[0]), "r"(a[1]), "r"(a[2]), "r"(a[3]), "r"(b[0]), "r"(b[1]));
}
__device__ __forceinline__ uint2 pack4bf(float4 r) {
    bf162 lo = __floats2bfloat162_rn(r.x, r.y);
    bf162 hi = __floats2bfloat162_rn(r.z, r.w);
    uint2 u;
    u.x = *(uint32_t*)&lo;
    u.y = *(uint32_t*)&hi;
    return u;
}

// ---------------- weight transpose: dst[n][k] = bf16(src[k][n]) --------------
__global__ void transpose_kernel(const float* __restrict__ src,
                                 bf16* __restrict__ dst, int K, int N) {
    __shared__ float tile[32][33];
    int n0 = blockIdx.x * 32, k0 = blockIdx.y * 32;
    int tx = threadIdx.x & 31, ty = threadIdx.x >> 5;
#pragma unroll
    for (int i = ty; i < 32; i += 8)
        tile[i][tx] = src[(size_t)(k0 + i) * N + n0 + tx];
    __syncthreads();
#pragma unroll
    for (int i = ty; i < 32; i += 8)
        dst[(size_t)(n0 + i) * K + k0 + tx] = __float2bfloat16(tile[tx][i]);
}

// ---------------- shift + window partition -----------------------------------
__device__ __forceinline__ int token_index(int d, int h, int w) {
    int win = ((d >> 2) * 8 + (h >> 3)) * 8 + (w >> 3);
    int tok = ((d & 3) << 6) + ((h & 7) << 3) + (w & 7);
    return (win << 8) + tok;
}

__global__ void window_gather_kernel(const float* __restrict__ x,
                                     float* __restrict__ xw) {
    __shared__ float sm[32][65];
    const int c0 = blockIdx.x * 32;
    const int h0 = blockIdx.y;
    const int d0 = blockIdx.z;
    const int tid = threadIdx.x;
    {
        int cl = tid >> 4;
        int v4 = (tid & 15) * 4;
        const float* xp = x + (size_t)(c0 + cl) * 65536 + d0 * 4096 + h0 * 64 + v4;
        float4 a = *(const float4*)xp;
        sm[cl][v4 + 0] = a.x; sm[cl][v4 + 1] = a.y;
        sm[cl][v4 + 2] = a.z; sm[cl][v4 + 3] = a.w;
        float4 b = *(const float4*)(xp + (size_t)16 * 65536);
        sm[cl + 16][v4 + 0] = b.x; sm[cl + 16][v4 + 1] = b.y;
        sm[cl + 16][v4 + 2] = b.z; sm[cl + 16][v4 + 3] = b.w;
    }
    __syncthreads();
    int w0 = tid >> 2;
    int cg = (tid & 3) * 8;
    int d = (d0 + 14) & 15;
    int h = (h0 + 60) & 63;
    int w = (w0 + 60) & 63;
    int n = token_index(d, h, w);
    float* op = xw + (size_t)n * CDIM + c0 + cg;
    float4 o0, o1;
    o0.x = sm[cg + 0][w0]; o0.y = sm[cg + 1][w0];
    o0.z = sm[cg + 2][w0]; o0.w = sm[cg + 3][w0];
    o1.x = sm[cg + 4][w0]; o1.y = sm[cg + 5][w0];
    o1.z = sm[cg + 6][w0]; o1.w = sm[cg + 7][w0];
    *(float4*)op = o0;
    *(float4*)(op + 4) = o1;
}

__global__ void window_scatter_kernel(const float* __restrict__ y,
                                      float* __restrict__ out) {
    __shared__ float sm[32][65];
    const int c0 = blockIdx.x * 32;
    const int h0 = blockIdx.y;
    const int d0 = blockIdx.z;
    const int tid = threadIdx.x;
    {
        int w0 = tid >> 2;
        int cg = (tid & 3) * 8;
        int d = (d0 + 14) & 15;
        int h = (h0 + 60) & 63;
        int w = (w0 + 60) & 63;
        int n = token_index(d, h, w);
        const float* ip = y + (size_t)n * CDIM + c0 + cg;
        float4 a = *(const float4*)ip;
        float4 b = *(const float4*)(ip + 4);
        sm[cg + 0][w0] = a.x; sm[cg + 1][w0] = a.y;
        sm[cg + 2][w0] = a.z; sm[cg + 3][w0] = a.w;
        sm[cg + 4][w0] = b.x; sm[cg + 5][w0] = b.y;
        sm[cg + 6][w0] = b.z; sm[cg + 7][w0] = b.w;
    }
    __syncthreads();
    int cl = tid >> 4;
    int v4 = (tid & 15) * 4;
    float* op = out + (size_t)(c0 + cl) * 65536 + d0 * 4096 + h0 * 64 + v4;
    float4 o;
    o.x = sm[cl][v4 + 0]; o.y = sm[cl][v4 + 1];
    o.z = sm[cl][v4 + 2]; o.w = sm[cl][v4 + 3];
    *(float4*)op = o;
    float4 p;
    p.x = sm[cl + 16][v4 + 0]; p.y = sm[cl + 16][v4 + 1];
    p.z = sm[cl + 16][v4 + 2]; p.w = sm[cl + 16][v4 + 3];
    *(float4*)(op + (size_t)16 * 65536) = p;
}

// ---------------- layernorm (fp32 in, bf16 out) ------------------------------
__global__ void ln_kernel(const float* __restrict__ x,
                          const float* __restrict__ gam,
                          const float* __restrict__ bet,
                          bf16* __restrict__ out) {
    int warp = threadIdx.x >> 5;
    int lane = threadIdx.x & 31;
    size_t n = (size_t)blockIdx.x * 8 + warp;
    const float4* xr = (const float4*)(x + n * CDIM);
    float4 v[3];
    float s = 0.f, ss = 0.f;
#pragma unroll
    for (int i = 0; i < 3; i++) {
        v[i] = xr[i * 32 + lane];
        s += v[i].x + v[i].y + v[i].z + v[i].w;
        ss += v[i].x * v[i].x + v[i].y * v[i].y + v[i].z * v[i].z + v[i].w * v[i].w;
    }
#pragma unroll
    for (int off = 16; off; off >>= 1) {
        s  += __shfl_xor_sync(0xffffffffu, s,  off);
        ss += __shfl_xor_sync(0xffffffffu, ss, off);
    }
    float mean = s * (1.0f / CDIM);
    float var  = ss * (1.0f / CDIM) - mean * mean;
    float rstd = rsqrtf(var + 1e-5f);
    const float4* G = (const float4*)gam;
    const float4* B = (const float4*)bet;
    uint2* o = (uint2*)(out + n * CDIM);
#pragma unroll
    for (int i = 0; i < 3; i++) {
        float4 g = G[i * 32 + lane];
        float4 b = B[i * 32 + lane];
        float4 r;
        r.x = (v[i].x - mean) * rstd * g.x + b.x;
        r.y = (v[i].y - mean) * rstd * g.y + b.y;
        r.z = (v[i].z - mean) * rstd * g.z + b.z;
        r.w = (v[i].w - mean) * rstd * g.w + b.w;
        o[i * 32 + lane] = pack4bf(r);
    }
}

// ---------------- BF16 mma.sync GEMM core ------------------------------------
// CTA 128x128, 8 warps (2x4), warp tile 64x32, K-stage 32 (2 x k16 blocks).
// smem rows: 16 bf16 in a 24-element (48B) slot; banks (12*gid+tig) distinct.
#define RS 24          // row stride (bf16 elements)
#define KBLK 3072      // 128*24 elements per k16 block
#define BUFE 6144      // elements per buffer (2 k16 blocks)

__device__ __forceinline__ void mma_tile(const bf16* __restrict__ A,
                                         const bf16* __restrict__ Bt,
                                         int K, int rowBase, int colBase,
                                         float acc[4][4][4]) {
    __shared__ __align__(16) bf16 sA[2 * BUFE];
    __shared__ __align__(16) bf16 sB[2 * BUFE];
    const int tid = threadIdx.x;
    const int nk = K >> 5;
    const int wid = tid >> 5, lane = tid & 31;
    const int gid = lane >> 2, tig = lane & 3;
    const int wr = (wid >> 2) * 64, wc = (wid & 3) * 32;

#pragma unroll
    for (int mt = 0; mt < 4; mt++)
#pragma unroll
        for (int nt = 0; nt < 4; nt++)
#pragma unroll
            for (int f = 0; f < 4; f++) acc[mt][nt][f] = 0.f;

    auto stage = [&](int ks, int buf) {
        const bf16* Ap = A + (size_t)rowBase * K + ks * 32;
        const bf16* Bp = Bt + (size_t)colBase * K + ks * 32;
#pragma unroll
        for (int i = 0; i < 2; i++) {
            int c = tid * 2 + i;            // 0..511
            int r = c >> 2, piece = c & 3;  // piece: 2 halves x 2 kblks
            int kb = piece >> 1, half = piece & 1;
            uint32_t dA = smem_u32(&sA[buf * BUFE + kb * KBLK + r * RS + half * 8]);
            uint32_t dB = smem_u32(&sB[buf * BUFE + kb * KBLK + r * RS + half * 8]);
            cp_async16(dA, Ap + (size_t)r * K + kb * 16 + half * 8);
            cp_async16(dB, Bp + (size_t)r * K + kb * 16 + half * 8);
        }
        cp_commit();
    };

    stage(0, 0);
    for (int k = 0; k < nk; k++) {
        int cur = k & 1;
        if (k + 1 < nk) { stage(k + 1, cur ^ 1); cp_wait<1>(); }
        else            { cp_wait<0>(); }
        __syncthreads();
        const bf16* a_s = sA + cur * BUFE;
        const bf16* b_s = sB + cur * BUFE;
#pragma unroll
        for (int kb = 0; kb < 2; kb++) {
            uint32_t af[4][4], bf[4][2];
#pragma unroll
            for (int mt = 0; mt < 4; mt++) {
                const bf16* p = a_s + kb * KBLK + (wr + mt * 16 + gid) * RS + 2 * tig;
                af[mt][0] = *(const uint32_t*)(p);
                af[mt][1] = *(const uint32_t*)(p + 8 * RS);
                af[mt][2] = *(const uint32_t*)(p + 8);
                af[mt][3] = *(const uint32_t*)(p + 8 * RS + 8);
            }
#pragma unroll
            for (int nt = 0; nt < 4; nt++) {
                const bf16* p = b_s + kb * KBLK + (wc + nt * 8 + gid) * RS + 2 * tig;
                bf[nt][0] = *(const uint32_t*)(p);
                bf[nt][1] = *(const uint32_t*)(p + 8);
            }
#pragma unroll
            for (int mt = 0; mt < 4; mt++)
#pragma unroll
                for (int nt = 0; nt < 4; nt++)
                    mma_bf16(acc[mt][nt], af[mt], bf[nt]);
        }
        __syncthreads();
    }
}

// ---- QKV GEMM: scatter fp32 to [win][head][t][64] ---------------------------
__global__ __launch_bounds__(256, 2)
void mm_qkv(const bf16* __restrict__ hb, const bf16* __restrict__ wt,
            const float* __restrict__ bq, const float* __restrict__ bk,
            const float* __restrict__ bv,
            float* __restrict__ q, float* __restrict__ k,
            float* __restrict__ v) {
    int g = blockIdx.z;
    const bf16* Bt = wt + (size_t)g * 147456;
    const float* bias = (g == 0) ? bq : (g == 1) ? bk : bv;
    float* out = (g == 0) ? q : (g == 1) ? k : v;
    int rowBase = blockIdx.y * 128, colBase = blockIdx.x * 128;

    float acc[4][4][4];
    mma_tile(hb, Bt, CDIM, rowBase, colBase, acc);

    const int lane = threadIdx.x & 31, wid = threadIdx.x >> 5;
    const int gid = lane >> 2, tig = lane & 3;
    const int wr = (wid >> 2) * 64, wc = (wid & 3) * 32;
#pragma unroll
    for (int mt = 0; mt < 4; mt++) {
        int r0 = rowBase + wr + mt * 16 + gid;
#pragma unroll
        for (int nt = 0; nt < 4; nt++) {
            int c = colBase + wc + nt * 8 + 2 * tig;
            int head = c >> 6, dd = c & 63;
            float bx = bias[c], by = bias[c + 1];
#pragma unroll
            for (int hh = 0; hh < 2; hh++) {
                int r = r0 + hh * 8;
                int win = r >> 8, t = r & 255;
                float2 o = make_float2(acc[mt][nt][2 * hh] + bx,
                                       acc[mt][nt][2 * hh + 1] + by);
                *(float2*)(out + (size_t)win * 98304 + head * 16384 +
                           t * 64 + dd) = o;
            }
        }
    }
}

// ---- GEMM + bias + residual (fp32 out) --------------------------------------
__global__ __launch_bounds__(256, 2)
void mm_biasres(const bf16* __restrict__ A, const bf16* __restrict__ Bt,
                const float* __restrict__ bias, const float* __restrict__ res,
                float* __restrict__ out, int K) {
    int rowBase = blockIdx.y * 128, colBase = blockIdx.x * 128;
    float acc[4][4][4];
    mma_tile(A, Bt, K, rowBase, colBase, acc);

    const int lane = threadIdx.x & 31, wid = threadIdx.x >> 5;
    const int gid = lane >> 2, tig = lane & 3;
    const int wr = (wid >> 2) * 64, wc = (wid & 3) * 32;
#pragma unroll
    for (int mt = 0; mt < 4; mt++) {
        int r0 = rowBase + wr + mt * 16 + gid;
#pragma unroll
        for (int nt = 0; nt < 4; nt++) {
            int c = colBase + wc + nt * 8 + 2 * tig;
            float bx = bias[c], by = bias[c + 1];
#pragma unroll
            for (int hh = 0; hh < 2; hh++) {
                size_t off = (size_t)(r0 + hh * 8) * CDIM + c;
                float2 rr = *(const float2*)(res + off);
                float2 o = make_float2(acc[mt][nt][2 * hh] + bx + rr.x,
                                       acc[mt][nt][2 * hh + 1] + by + rr.y);
                *(float2*)(out + off) = o;
            }
        }
    }
}

// ---- GEMM + bias + exact GELU (bf16 out, N=1536) ----------------------------
__device__ __forceinline__ float gelu_f(float v) {
    return 0.5f * v * (1.0f + erff(v * 0.70710678118654752440f));
}

__global__ __launch_bounds__(256, 2)
void mm_gelu(const bf16* __restrict__ A, const bf16* __restrict__ Bt,
             const float* __restrict__ bias, bf16* __restrict__ out) {
    int rowBase = blockIdx.y * 128, colBase = blockIdx.x * 128;
    float acc[4][4][4];
    mma_tile(A, Bt, CDIM, rowBase, colBase, acc);

    const int lane = threadIdx.x & 31, wid = threadIdx.x >> 5;
    const int gid = lane >> 2, tig = lane & 3;
    const int wr = (wid >> 2) * 64, wc = (wid & 3) * 32;
#pragma unroll
    for (int mt = 0; mt < 4; mt++) {
        int r0 = rowBase + wr + mt * 16 + gid;
#pragma unroll
        for (int nt = 0; nt < 4; nt++) {
            int c = colBase + wc + nt * 8 + 2 * tig;
            float bx = bias[c], by = bias[c + 1];
#pragma unroll
            for (int hh = 0; hh < 2; hh++) {
                size_t off = (size_t)(r0 + hh * 8) * MLPD + c;
                bf162 o = __floats2bfloat162_rn(
                    gelu_f(acc[mt][nt][2 * hh] + bx),
                    gelu_f(acc[mt][nt][2 * hh + 1] + by));
                *(bf162*)(out + off) = o;
            }
        }
    }
}

// ---------------- attention via mma.sync TF32 (bf16 out) ---------------------
#define KSTR 68
#define VSTR 72
#define ATT_SMEM ((256 * KSTR + 256 * VSTR + 256 * KSTR) * 4)

__global__ __launch_bounds__(256, 1)
void attn_mma(const float* __restrict__ q, const float* __restrict__ k,
              const float* __restrict__ v, bf16* __restrict__ out) {
    extern __shared__ float sm[];
    float* Ks = sm;
    float* Vs = sm + 256 * KSTR;
    float* Ps = Vs + 256 * VSTR;
    const int wh = blockIdx.x;
    const size_t base = (size_t)wh * 16384;
    const int tid = threadIdx.x;
    const int wid = tid >> 5, lane = tid & 31;
    const int gid = lane >> 2, tig = lane & 3;
    const int qr = wid * 32;
    float* Pw = Ps + wid * 32 * KSTR;

    {
        const float4* Kg = (const float4*)(k + base + tid * 64);
        const float4* Vg = (const float4*)(v + base + tid * 64);
        const float4* Qg = (const float4*)(q + base + tid * 64);
#pragma unroll
        for (int i = 0; i < 16; i++) {
            float4 a = Kg[i];
            Ks[tid * KSTR + 4 * i + 0] = tf32r(a.x);
            Ks[tid * KSTR + 4 * i + 1] = tf32r(a.y);
            Ks[tid * KSTR + 4 * i + 2] = tf32r(a.z);
            Ks[tid * KSTR + 4 * i + 3] = tf32r(a.w);
            float4 b = Vg[i];
            Vs[tid * VSTR + 4 * i + 0] = tf32r(b.x);
            Vs[tid * VSTR + 4 * i + 1] = tf32r(b.y);
            Vs[tid * VSTR + 4 * i + 2] = tf32r(b.z);
            Vs[tid * VSTR + 4 * i + 3] = tf32r(b.w);
            float4 c = Qg[i];
            Ps[tid * KSTR + 4 * i + 0] = tf32r(c.x * 0.125f);
            Ps[tid * KSTR + 4 * i + 1] = tf32r(c.y * 0.125f);
            Ps[tid * KSTR + 4 * i + 2] = tf32r(c.z * 0.125f);
            Ps[tid * KSTR + 4 * i + 3] = tf32r(c.w * 0.125f);
        }
    }
    __syncthreads();

    uint32_t qf[2][8][4];
#pragma unroll
    for (int mt = 0; mt < 2; mt++)
#pragma unroll
        for (int ks = 0; ks < 8; ks++) {
            const float* p = Ps + (qr + mt * 16 + gid) * KSTR + ks * 8 + tig;
            qf[mt][ks][0] = __float_as_uint(p[0]);
            qf[mt][ks][1] = __float_as_uint(p[8 * KSTR]);
            qf[mt][ks][2] = __float_as_uint(p[4]);
            qf[mt][ks][3] = __float_as_uint(p[8 * KSTR + 4]);
        }
    __syncthreads();

    float oacc[2][8][4];
#pragma unroll
    for (int mt = 0; mt < 2; mt++)
#pragma unroll
        for (int nt = 0; nt < 8; nt++)
#pragma unroll
            for (int f = 0; f < 4; f++) oacc[mt][nt][f] = 0.f;
    float mrow[2][2] = {{-1e30f, -1e30f}, {-1e30f, -1e30f}};
    float lrow[2][2] = {{0.f, 0.f}, {0.f, 0.f}};

    for (int jb = 0; jb < 4; jb++) {
        float sacc[2][8][4];
#pragma unroll
        for (int mt = 0; mt < 2; mt++)
#pragma unroll
            for (int nt = 0; nt < 8; nt++)
#pragma unroll
                for (int f = 0; f < 4; f++) sacc[mt][nt][f] = 0.f;
#pragma unroll
        for (int ks = 0; ks < 8; ks++) {
            uint32_t kf[8][2];
#pragma unroll
            for (int nt = 0; nt < 8; nt++) {
                const float* p = Ks + (jb * 64 + nt * 8 + gid) * KSTR + ks * 8 + tig;
                kf[nt][0] = __float_as_uint(p[0]);
                kf[nt][1] = __float_as_uint(p[4]);
            }
#pragma unroll
            for (int mt = 0; mt < 2; mt++)
#pragma unroll
                for (int nt = 0; nt < 8; nt++)
                    mma_tf32(sacc[mt][nt], qf[mt][ks], kf[nt]);
        }

        __syncwarp();
#pragma unroll
        for (int mt = 0; mt < 2; mt++)
#pragma unroll
            for (int hh = 0; hh < 2; hh++) {
                float bm = -1e30f;
#pragma unroll
                for (int nt = 0; nt < 8; nt++) {
                    bm = fmaxf(bm, sacc[mt][nt][2 * hh]);
                    bm = fmaxf(bm, sacc[mt][nt][2 * hh + 1]);
                }
                bm = fmaxf(bm, __shfl_xor_sync(0xffffffffu, bm, 1));
                bm = fmaxf(bm, __shfl_xor_sync(0xffffffffu, bm, 2));
                float mn = fmaxf(mrow[mt][hh], bm);
                float scale = __expf(mrow[mt][hh] - mn);
                mrow[mt][hh] = mn;
                lrow[mt][hh] *= scale;
#pragma unroll
                for (int nt = 0; nt < 8; nt++) {
                    oacc[mt][nt][2 * hh]     *= scale;
                    oacc[mt][nt][2 * hh + 1] *= scale;
                }
                float psum = 0.f;
                int row = mt * 16 + gid + hh * 8;
#pragma unroll
                for (int nt = 0; nt < 8; nt++) {
                    float p0 = tf32r(__expf(sacc[mt][nt][2 * hh]     - mn));
                    float p1 = tf32r(__expf(sacc[mt][nt][2 * hh + 1] - mn));
                    psum += p0 + p1;
                    *(float2*)(Pw + row * KSTR + nt * 8 + 2 * tig) =
                        make_float2(p0, p1);
                }
                psum += __shfl_xor_sync(0xffffffffu, psum, 1);
                psum += __shfl_xor_sync(0xffffffffu, psum, 2);
                lrow[mt][hh] += psum;
            }
        __syncwarp();

#pragma unroll
        for (int ks = 0; ks < 8; ks++) {
            uint32_t pf[2][4], vf[8][2];
#pragma unroll
            for (int mt = 0; mt < 2; mt++) {
                const float* p = Pw + (mt * 16 + gid) * KSTR + ks * 8 + tig;
                pf[mt][0] = __float_as_uint(p[0]);
                pf[mt][1] = __float_as_uint(p[8 * KSTR]);
                pf[mt][2] = __float_as_uint(p[4]);
                pf[mt][3] = __float_as_uint(p[8 * KSTR + 4]);
            }
#pragma unroll
            for (int nt = 0; nt < 8; nt++) {
                const float* p = Vs + (jb * 64 + ks * 8 + tig) * VSTR + nt * 8 + gid;
                vf[nt][0] = __float_as_uint(p[0]);
                vf[nt][1] = __float_as_uint(p[4 * VSTR]);
            }
#pragma unroll
            for (int mt = 0; mt < 2; mt++)
#pragma unroll
                for (int nt = 0; nt < 8; nt++)
                    mma_tf32(oacc[mt][nt], pf[mt], vf[nt]);
        }
    }

    const int win = wh / 6, head = wh % 6;
#pragma unroll
    for (int mt = 0; mt < 2; mt++)
#pragma unroll
        for (int hh = 0; hh < 2; hh++) {
            float inv = 1.0f / lrow[mt][hh];
            int row = qr + mt * 16 + gid + hh * 8;
            bf16* op = out + ((size_t)win * 256 + row) * CDIM + head * 64;
#pragma unroll
            for (int nt = 0; nt < 8; nt++) {
                bf162 o = __floats2bfloat162_rn(
                    oacc[mt][nt][2 * hh] * inv,
                    oacc[mt][nt][2 * hh + 1] * inv);
                *(bf162*)(op + nt * 8 + 2 * tig) = o;
            }
        }
}

// ---------------------------------------------------------------------------
extern "C" void kernel_launch(void* const* d_in, const int* in_sizes, int n_in,
                              void* d_out, int out_size) {
    (void)in_sizes; (void)n_in; (void)out_size;
    const float* x   = (const float*)d_in[0];
    const float* Wq  = (const float*)d_in[1];
    const float* bq  = (const float*)d_in[2];
    const float* Wk  = (const float*)d_in[3];
    const float* bk  = (const float*)d_in[4];
    const float* Wv  = (const float*)d_in[5];
    const float* bv  = (const float*)d_in[6];
    const float* Wo  = (const float*)d_in[7];
    const float* bo  = (const float*)d_in[8];
    const float* g1  = (const float*)d_in[9];
    const float* be1 = (const float*)d_in[10];
    const float* g2  = (const float*)d_in[11];
    const float* be2 = (const float*)d_in[12];
    const float* W1  = (const float*)d_in[13];
    const float* B1  = (const float*)d_in[14];
    const float* W2  = (const float*)d_in[15];
    const float* B2  = (const float*)d_in[16];
    float* out = (float*)d_out;

    float *xw, *qb, *kb, *vb, *x2;
    bf16 *hb, *att, *mlp, *wt;
    cudaGetSymbolAddress((void**)&xw,  g_xw);
    cudaGetSymbolAddress((void**)&hb,  g_h);
    cudaGetSymbolAddress((void**)&qb,  g_q);
    cudaGetSymbolAddress((void**)&kb,  g_k);
    cudaGetSymbolAddress((void**)&vb,  g_v);
    cudaGetSymbolAddress((void**)&att, g_att);
    cudaGetSymbolAddress((void**)&x2,  g_x2);
    cudaGetSymbolAddress((void**)&mlp, g_mlp);
    cudaGetSymbolAddress((void**)&wt,  g_wt);

    cudaFuncSetAttribute(attn_mma,
                         cudaFuncAttributeMaxDynamicSharedMemorySize, ATT_SMEM);

    // 0) weight transposes to K-major bf16
    transpose_kernel<<<dim3(12, 12), 256>>>(Wq, wt + 0,       CDIM, CDIM);
    transpose_kernel<<<dim3(12, 12), 256>>>(Wk, wt + 147456,  CDIM, CDIM);
    transpose_kernel<<<dim3(12, 12), 256>>>(Wv, wt + 294912,  CDIM, CDIM);
    transpose_kernel<<<dim3(12, 12), 256>>>(Wo, wt + 442368,  CDIM, CDIM);
    transpose_kernel<<<dim3(48, 12), 256>>>(W1, wt + 589824,  CDIM, MLPD);
    transpose_kernel<<<dim3(12, 48), 256>>>(W2, wt + 1179648, MLPD, CDIM);

    // 1) shift + window partition (fp32 residual stream)
    window_gather_kernel<<<dim3(12, 64, 16), 256>>>(x, xw);
    // 2) LN1 -> bf16
    ln_kernel<<<8192, 256>>>(xw, g1, be1, hb);
    // 3) QKV projections (bf16 mma) -> fp32 [win][head][t][64]
    mm_qkv<<<dim3(3, 512, 3), 256>>>(hb, wt, bq, bk, bv, qb, kb, vb);
    // 4) windowed attention (tf32 mma flash) -> bf16 token-major
    attn_mma<<<1536, 256, ATT_SMEM>>>(qb, kb, vb, att);
    // 5) output projection + residual -> fp32
    mm_biasres<<<dim3(3, 512), 256>>>(att, wt + 442368, bo, xw, x2, CDIM);
    // 6) LN2 -> bf16
    ln_kernel<<<8192, 256>>>(x2, g2, be2, hb);
    // 7) MLP up + GELU -> bf16
    mm_gelu<<<dim3(12, 512), 256>>>(hb, wt + 589824, B1, mlp);
    // 8) MLP down + residual -> fp32 (reuse qb)
    mm_biasres<<<dim3(3, 512), 256>>>(mlp, wt + 1179648, B2, x2, qb, MLPD);
    // 9) reverse window partition + shift
    window_scatter_kernel<<<dim3(12, 64, 16), 256>>>(qb, out);
}

// round 8
// speedup vs baseline: 3.5556x; 1.0933x over previous
#include <cuda_runtime.h>
#include <cuda_bf16.h>
#include <math.h>
#include <stdint.h>

// ---------------------------------------------------------------------------
// SwinBlock3D: GEMMs via mma.sync BF16 (ldmatrix fragment loads), attention
// via mma.sync TF32 flash with bf16 q/k/v. x(1,384,16,64,64) HEADS=6 MLP=1536
// ---------------------------------------------------------------------------

#define NTOK 65536
#define CDIM 384
#define MLPD 1536

typedef __nv_bfloat16 bf16;
typedef __nv_bfloat162 bf162;

__device__ float g_xw [(size_t)NTOK * CDIM];   // fp32 residual stream
__device__ bf16  g_h  [(size_t)NTOK * CDIM];   // LN outputs (bf16 GEMM A)
__device__ bf16  g_q  [(size_t)NTOK * CDIM];
__device__ bf16  g_k  [(size_t)NTOK * CDIM];
__device__ bf16  g_v  [(size_t)NTOK * CDIM];
__device__ bf16  g_att[(size_t)NTOK * CDIM];   // attention out (bf16 GEMM A)
__device__ float g_x2 [(size_t)NTOK * CDIM];   // fp32 residual stream
__device__ bf16  g_mlp[(size_t)NTOK * MLPD];   // GELU out (bf16 GEMM A)
__device__ float g_y  [(size_t)NTOK * CDIM];   // final pre-scatter fp32
// transposed (K-major) bf16 weights: qkv(3x147456) | o | w1 | w2
__device__ bf16  g_wt [1769472];

// ---------------- helpers ----------------------------------------------------
__device__ __forceinline__ float tf32r(float x) {
    uint32_t u;
    asm("cvt.rna.tf32.f32 %0, %1;" : "=r"(u) : "f"(x));
    return __uint_as_float(u);
}
__device__ __forceinline__ uint32_t smem_u32(const void* p) {
    uint32_t a;
    asm("{ .reg .u64 t; cvta.to.shared.u64 t, %1; cvt.u32.u64 %0, t; }"
        : "=r"(a) : "l"(p));
    return a;
}
__device__ __forceinline__ void cp_async16(uint32_t s, const void* g) {
    asm volatile("cp.async.cg.shared.global [%0], [%1], 16;" :: "r"(s), "l"(g));
}
__device__ __forceinline__ void cp_commit() {
    asm volatile("cp.async.commit_group;");
}
template<int N> __device__ __forceinline__ void cp_wait() {
    asm volatile("cp.async.wait_group %0;" :: "n"(N));
}
__device__ __forceinline__ void ldm_x4(uint32_t r[4], uint32_t addr) {
    asm volatile("ldmatrix.sync.aligned.m8n8.x4.shared.b16 {%0,%1,%2,%3}, [%4];"
                 : "=r"(r[0]), "=r"(r[1]), "=r"(r[2]), "=r"(r[3]) : "r"(addr));
}
__device__ __forceinline__ void mma_bf16(float c[4], const uint32_t a[4],
                                         const uint32_t b[2]) {
    asm volatile(
        "mma.sync.aligned.m16n8k16.row.col.f32.bf16.bf16.f32 "
        "{%0,%1,%2,%3}, {%4,%5,%6,%7}, {%8,%9}, {%0,%1,%2,%3};"
        : "+f"(c[0]), "+f"(c[1]), "+f"(c[2]), "+f"(c[3])
        : "r"(a[0]), "r"(a[1]), "r"(a[2]), "r"(a[3]), "r"(b[0]), "r"(b[1]));
}
__device__ __forceinline__ void mma_tf32(float c[4], const uint32_t a[4],
                                         const uint32_t b[2]) {
    asm volatile(
        "mma.sync.aligned.m16n8k8.row.col.f32.tf32.tf32.f32 "
        "{%0,%1,%2,%3}, {%4,%5,%6,%7}, {%8,%9}, {%0,%1,%2,%3};"
        : "+f"(c[0]), "+f"(c[1]), "+f"(c[2]), "+f"(c[3])
        : "r"(a[0]), "r"(a[1]), "r"(a[2]), "r"(a[3]), "r"(b[0]), "r"(b[1]));
}
__device__ __forceinline__ uint2 pack4bf(float4 r) {
    bf162 lo = __floats2bfloat162_rn(r.x, r.y);
    bf162 hi = __floats2bfloat162_rn(r.z, r.w);
    uint2 u;
    u.x = *(uint32_t*)&lo;
    u.y = *(uint32_t*)&hi;
    return u;
}

// ---------------- weight transpose: dst[n][k] = bf16(src[k][n]) --------------
__global__ void transpose_kernel(const float* __restrict__ src,
                                 bf16* __restrict__ dst, int K, int N) {
    __shared__ float tile[32][33];
    int n0 = blockIdx.x * 32, k0 = blockIdx.y * 32;
    int tx = threadIdx.x & 31, ty = threadIdx.x >> 5;
#pragma unroll
    for (int i = ty; i < 32; i += 8)
        tile[i][tx] = src[(size_t)(k0 + i) * N + n0 + tx];
    __syncthreads();
#pragma unroll
    for (int i = ty; i < 32; i += 8)
        dst[(size_t)(n0 + i) * K + k0 + tx] = __float2bfloat16(tile[tx][i]);
}

// ---------------- shift + window partition -----------------------------------
__device__ __forceinline__ int token_index(int d, int h, int w) {
    int win = ((d >> 2) * 8 + (h >> 3)) * 8 + (w >> 3);
    int tok = ((d & 3) << 6) + ((h & 7) << 3) + (w & 7);
    return (win << 8) + tok;
}

__global__ void window_gather_kernel(const float* __restrict__ x,
                                     float* __restrict__ xw) {
    __shared__ float sm[32][65];
    const int c0 = blockIdx.x * 32;
    const int h0 = blockIdx.y;
    const int d0 = blockIdx.z;
    const int tid = threadIdx.x;
    {
        int cl = tid >> 4;
        int v4 = (tid & 15) * 4;
        const float* xp = x + (size_t)(c0 + cl) * 65536 + d0 * 4096 + h0 * 64 + v4;
        float4 a = *(const float4*)xp;
        sm[cl][v4 + 0] = a.x; sm[cl][v4 + 1] = a.y;
        sm[cl][v4 + 2] = a.z; sm[cl][v4 + 3] = a.w;
        float4 b = *(const float4*)(xp + (size_t)16 * 65536);
        sm[cl + 16][v4 + 0] = b.x; sm[cl + 16][v4 + 1] = b.y;
        sm[cl + 16][v4 + 2] = b.z; sm[cl + 16][v4 + 3] = b.w;
    }
    __syncthreads();
    int w0 = tid >> 2;
    int cg = (tid & 3) * 8;
    int d = (d0 + 14) & 15;
    int h = (h0 + 60) & 63;
    int w = (w0 + 60) & 63;
    int n = token_index(d, h, w);
    float* op = xw + (size_t)n * CDIM + c0 + cg;
    float4 o0, o1;
    o0.x = sm[cg + 0][w0]; o0.y = sm[cg + 1][w0];
    o0.z = sm[cg + 2][w0]; o0.w = sm[cg + 3][w0];
    o1.x = sm[cg + 4][w0]; o1.y = sm[cg + 5][w0];
    o1.z = sm[cg + 6][w0]; o1.w = sm[cg + 7][w0];
    *(float4*)op = o0;
    *(float4*)(op + 4) = o1;
}

__global__ void window_scatter_kernel(const float* __restrict__ y,
                                      float* __restrict__ out) {
    __shared__ float sm[32][65];
    const int c0 = blockIdx.x * 32;
    const int h0 = blockIdx.y;
    const int d0 = blockIdx.z;
    const int tid = threadIdx.x;
    {
        int w0 = tid >> 2;
        int cg = (tid & 3) * 8;
        int d = (d0 + 14) & 15;
        int h = (h0 + 60) & 63;
        int w = (w0 + 60) & 63;
        int n = token_index(d, h, w);
        const float* ip = y + (size_t)n * CDIM + c0 + cg;
        float4 a = *(const float4*)ip;
        float4 b = *(const float4*)(ip + 4);
        sm[cg + 0][w0] = a.x; sm[cg + 1][w0] = a.y;
        sm[cg + 2][w0] = a.z; sm[cg + 3][w0] = a.w;
        sm[cg + 4][w0] = b.x; sm[cg + 5][w0] = b.y;
        sm[cg + 6][w0] = b.z; sm[cg + 7][w0] = b.w;
    }
    __syncthreads();
    int cl = tid >> 4;
    int v4 = (tid & 15) * 4;
    float* op = out + (size_t)(c0 + cl) * 65536 + d0 * 4096 + h0 * 64 + v4;
    float4 o;
    o.x = sm[cl][v4 + 0]; o.y = sm[cl][v4 + 1];
    o.z = sm[cl][v4 + 2]; o.w = sm[cl][v4 + 3];
    *(float4*)op = o;
    float4 p;
    p.x = sm[cl + 16][v4 + 0]; p.y = sm[cl + 16][v4 + 1];
    p.z = sm[cl + 16][v4 + 2]; p.w = sm[cl + 16][v4 + 3];
    *(float4*)(op + (size_t)16 * 65536) = p;
}

// ---------------- layernorm (fp32 in, bf16 out) ------------------------------
__global__ void ln_kernel(const float* __restrict__ x,
                          const float* __restrict__ gam,
                          const float* __restrict__ bet,
                          bf16* __restrict__ out) {
    int warp = threadIdx.x >> 5;
    int lane = threadIdx.x & 31;
    size_t n = (size_t)blockIdx.x * 8 + warp;
    const float4* xr = (const float4*)(x + n * CDIM);
    float4 v[3];
    float s = 0.f, ss = 0.f;
#pragma unroll
    for (int i = 0; i < 3; i++) {
        v[i] = xr[i * 32 + lane];
        s += v[i].x + v[i].y + v[i].z + v[i].w;
        ss += v[i].x * v[i].x + v[i].y * v[i].y + v[i].z * v[i].z + v[i].w * v[i].w;
    }
#pragma unroll
    for (int off = 16; off; off >>= 1) {
        s  += __shfl_xor_sync(0xffffffffu, s,  off);
        ss += __shfl_xor_sync(0xffffffffu, ss, off);
    }
    float mean = s * (1.0f / CDIM);
    float var  = ss * (1.0f / CDIM) - mean * mean;
    float rstd = rsqrtf(var + 1e-5f);
    const float4* G = (const float4*)gam;
    const float4* B = (const float4*)bet;
    uint2* o = (uint2*)(out + n * CDIM);
#pragma unroll
    for (int i = 0; i < 3; i++) {
        float4 g = G[i * 32 + lane];
        float4 b = B[i * 32 + lane];
        float4 r;
        r.x = (v[i].x - mean) * rstd * g.x + b.x;
        r.y = (v[i].y - mean) * rstd * g.y + b.y;
        r.z = (v[i].z - mean) * rstd * g.z + b.z;
        r.w = (v[i].w - mean) * rstd * g.w + b.w;
        o[i * 32 + lane] = pack4bf(r);
    }
}

// ---------------- BF16 mma.sync GEMM core (ldmatrix fragments) ---------------
// CTA 128x128, 8 warps (2x4), warp tile 64x32, K-stage 32 (2 x k16 blocks).
// smem rows: 16 bf16 in a 24-element (48B) slot; ldmatrix phases conflict-free.
#define RS 24
#define KBLK 3072
#define BUFE 6144

__device__ __forceinline__ void mma_tile(const bf16* __restrict__ A,
                                         const bf16* __restrict__ Bt,
                                         int K, int rowBase, int colBase,
                                         float acc[4][4][4]) {
    __shared__ __align__(16) bf16 sA[2 * BUFE];
    __shared__ __align__(16) bf16 sB[2 * BUFE];
    const int tid = threadIdx.x;
    const int nk = K >> 5;
    const int wid = tid >> 5, lane = tid & 31;
    const int wr = (wid >> 2) * 64, wc = (wid & 3) * 32;
    // ldmatrix lane-address components
    const int arow = wr + (lane & 15);          // + mt*16
    const int ahalf = (lane >> 4) * 8;
    const int brow = wc + (lane & 7) + ((lane >> 4) << 3);   // + nh*16
    const int bhalf = ((lane >> 3) & 1) * 8;

#pragma unroll
    for (int mt = 0; mt < 4; mt++)
#pragma unroll
        for (int nt = 0; nt < 4; nt++)
#pragma unroll
            for (int f = 0; f < 4; f++) acc[mt][nt][f] = 0.f;

    auto stage = [&](int ks, int buf) {
        const bf16* Ap = A + (size_t)rowBase * K + ks * 32;
        const bf16* Bp = Bt + (size_t)colBase * K + ks * 32;
#pragma unroll
        for (int i = 0; i < 2; i++) {
            int c = tid * 2 + i;
            int r = c >> 2, piece = c & 3;
            int kb = piece >> 1, half = piece & 1;
            uint32_t dA = smem_u32(&sA[buf * BUFE + kb * KBLK + r * RS + half * 8]);
            uint32_t dB = smem_u32(&sB[buf * BUFE + kb * KBLK + r * RS + half * 8]);
            cp_async16(dA, Ap + (size_t)r * K + kb * 16 + half * 8);
            cp_async16(dB, Bp + (size_t)r * K + kb * 16 + half * 8);
        }
        cp_commit();
    };

    stage(0, 0);
    for (int k = 0; k < nk; k++) {
        int cur = k & 1;
        if (k + 1 < nk) { stage(k + 1, cur ^ 1); cp_wait<1>(); }
        else            { cp_wait<0>(); }
        __syncthreads();
        uint32_t aB = smem_u32(sA + cur * BUFE);
        uint32_t bB = smem_u32(sB + cur * BUFE);
#pragma unroll
        for (int kb = 0; kb < 2; kb++) {
            uint32_t af[4][4], bb[2][4];
#pragma unroll
            for (int mt = 0; mt < 4; mt++)
                ldm_x4(af[mt], aB + (uint32_t)((kb * KBLK +
                         (arow + mt * 16) * RS + ahalf) * 2));
#pragma unroll
            for (int nh = 0; nh < 2; nh++)
                ldm_x4(bb[nh], bB + (uint32_t)((kb * KBLK +
                         (brow + nh * 16) * RS + bhalf) * 2));
#pragma unroll
            for (int mt = 0; mt < 4; mt++)
#pragma unroll
                for (int nt = 0; nt < 4; nt++)
                    mma_bf16(acc[mt][nt], af[mt], &bb[nt >> 1][(nt & 1) * 2]);
        }
        __syncthreads();
    }
}

// ---- QKV GEMM: scatter bf16 to [win][head][t][64] ---------------------------
__global__ __launch_bounds__(256, 2)
void mm_qkv(const bf16* __restrict__ hb, const bf16* __restrict__ wt,
            const float* __restrict__ bq, const float* __restrict__ bk,
            const float* __restrict__ bv,
            bf16* __restrict__ q, bf16* __restrict__ k,
            bf16* __restrict__ v) {
    int g = blockIdx.z;
    const bf16* Bt = wt + (size_t)g * 147456;
    const float* bias = (g == 0) ? bq : (g == 1) ? bk : bv;
    bf16* out = (g == 0) ? q : (g == 1) ? k : v;
    int rowBase = blockIdx.y * 128, colBase = blockIdx.x * 128;

    float acc[4][4][4];
    mma_tile(hb, Bt, CDIM, rowBase, colBase, acc);

    const int lane = threadIdx.x & 31, wid = threadIdx.x >> 5;
    const int gid = lane >> 2, tig = lane & 3;
    const int wr = (wid >> 2) * 64, wc = (wid & 3) * 32;
#pragma unroll
    for (int mt = 0; mt < 4; mt++) {
        int r0 = rowBase + wr + mt * 16 + gid;
#pragma unroll
        for (int nt = 0; nt < 4; nt++) {
            int c = colBase + wc + nt * 8 + 2 * tig;
            int head = c >> 6, dd = c & 63;
            float bx = bias[c], by = bias[c + 1];
#pragma unroll
            for (int hh = 0; hh < 2; hh++) {
                int r = r0 + hh * 8;
                int win = r >> 8, t = r & 255;
                bf162 o = __floats2bfloat162_rn(acc[mt][nt][2 * hh] + bx,
                                                acc[mt][nt][2 * hh + 1] + by);
                *(bf162*)(out + (size_t)win * 98304 + head * 16384 +
                          t * 64 + dd) = o;
            }
        }
    }
}

// ---- GEMM + bias + residual (fp32 out) --------------------------------------
__global__ __launch_bounds__(256, 2)
void mm_biasres(const bf16* __restrict__ A, const bf16* __restrict__ Bt,
                const float* __restrict__ bias, const float* __restrict__ res,
                float* __restrict__ out, int K) {
    int rowBase = blockIdx.y * 128, colBase = blockIdx.x * 128;
    float acc[4][4][4];
    mma_tile(A, Bt, K, rowBase, colBase, acc);

    const int lane = threadIdx.x & 31, wid = threadIdx.x >> 5;
    const int gid = lane >> 2, tig = lane & 3;
    const int wr = (wid >> 2) * 64, wc = (wid & 3) * 32;
#pragma unroll
    for (int mt = 0; mt < 4; mt++) {
        int r0 = rowBase + wr + mt * 16 + gid;
#pragma unroll
        for (int nt = 0; nt < 4; nt++) {
            int c = colBase + wc + nt * 8 + 2 * tig;
            float bx = bias[c], by = bias[c + 1];
#pragma unroll
            for (int hh = 0; hh < 2; hh++) {
                size_t off = (size_t)(r0 + hh * 8) * CDIM + c;
                float2 rr = *(const float2*)(res + off);
                float2 o = make_float2(acc[mt][nt][2 * hh] + bx + rr.x,
                                       acc[mt][nt][2 * hh + 1] + by + rr.y);
                *(float2*)(out + off) = o;
            }
        }
    }
}

// ---- GEMM + bias + exact GELU (bf16 out, N=1536) ----------------------------
__device__ __forceinline__ float gelu_f(float v) {
    return 0.5f * v * (1.0f + erff(v * 0.70710678118654752440f));
}

__global__ __launch_bounds__(256, 2)
void mm_gelu(const bf16* __restrict__ A, const bf16* __restrict__ Bt,
             const float* __restrict__ bias, bf16* __restrict__ out) {
    int rowBase = blockIdx.y * 128, colBase = blockIdx.x * 128;
    float acc[4][4][4];
    mma_tile(A, Bt, CDIM, rowBase, colBase, acc);

    const int lane = threadIdx.x & 31, wid = threadIdx.x >> 5;
    const int gid = lane >> 2, tig = lane & 3;
    const int wr = (wid >> 2) * 64, wc = (wid & 3) * 32;
#pragma unroll
    for (int mt = 0; mt < 4; mt++) {
        int r0 = rowBase + wr + mt * 16 + gid;
#pragma unroll
        for (int nt = 0; nt < 4; nt++) {
            int c = colBase + wc + nt * 8 + 2 * tig;
            float bx = bias[c], by = bias[c + 1];
#pragma unroll
            for (int hh = 0; hh < 2; hh++) {
                size_t off = (size_t)(r0 + hh * 8) * MLPD + c;
                bf162 o = __floats2bfloat162_rn(
                    gelu_f(acc[mt][nt][2 * hh] + bx),
                    gelu_f(acc[mt][nt][2 * hh + 1] + by));
                *(bf162*)(out + off) = o;
            }
        }
    }
}

// ---------------- attention via mma.sync TF32 (bf16 in/out) ------------------
#define KSTR 68
#define VSTR 72
#define ATT_SMEM ((256 * KSTR + 256 * VSTR + 256 * KSTR) * 4)

__global__ __launch_bounds__(256, 1)
void attn_mma(const bf16* __restrict__ q, const bf16* __restrict__ k,
              const bf16* __restrict__ v, bf16* __restrict__ out) {
    extern __shared__ float sm[];
    float* Ks = sm;
    float* Vs = sm + 256 * KSTR;
    float* Ps = Vs + 256 * VSTR;
    const int wh = blockIdx.x;
    const size_t base = (size_t)wh * 16384;
    const int tid = threadIdx.x;
    const int wid = tid >> 5, lane = tid & 31;
    const int gid = lane >> 2, tig = lane & 3;
    const int qr = wid * 32;
    float* Pw = Ps + wid * 32 * KSTR;

    // stage K, V, Q (bf16 -> fp32; bf16 values are tf32-exact)
    {
        const uint4* Kg = (const uint4*)(k + base + tid * 64);
        const uint4* Vg = (const uint4*)(v + base + tid * 64);
        const uint4* Qg = (const uint4*)(q + base + tid * 64);
#pragma unroll
        for (int i = 0; i < 8; i++) {
            uint4 a = Kg[i];
            const bf162* ap = (const bf162*)&a;
#pragma unroll
            for (int j = 0; j < 4; j++) {
                float2 f = __bfloat1622float2(ap[j]);
                Ks[tid * KSTR + 8 * i + 2 * j]     = f.x;
                Ks[tid * KSTR + 8 * i + 2 * j + 1] = f.y;
            }
            uint4 b = Vg[i];
            const bf162* bp = (const bf162*)&b;
#pragma unroll
            for (int j = 0; j < 4; j++) {
                float2 f = __bfloat1622float2(bp[j]);
                Vs[tid * VSTR + 8 * i + 2 * j]     = f.x;
                Vs[tid * VSTR + 8 * i + 2 * j + 1] = f.y;
            }
            uint4 cq = Qg[i];
            const bf162* cp = (const bf162*)&cq;
#pragma unroll
            for (int j = 0; j < 4; j++) {
                float2 f = __bfloat1622float2(cp[j]);
                Ps[tid * KSTR + 8 * i + 2 * j]     = f.x * 0.125f;
                Ps[tid * KSTR + 8 * i + 2 * j + 1] = f.y * 0.125f;
            }
        }
    }
    __syncthreads();

    uint32_t qf[2][8][4];
#pragma unroll
    for (int mt = 0; mt < 2; mt++)
#pragma unroll
        for (int ks = 0; ks < 8; ks++) {
            const float* p = Ps + (qr + mt * 16 + gid) * KSTR + ks * 8 + tig;
            qf[mt][ks][0] = __float_as_uint(p[0]);
            qf[mt][ks][1] = __float_as_uint(p[8 * KSTR]);
            qf[mt][ks][2] = __float_as_uint(p[4]);
            qf[mt][ks][3] = __float_as_uint(p[8 * KSTR + 4]);
        }
    __syncthreads();

    float oacc[2][8][4];
#pragma unroll
    for (int mt = 0; mt < 2; mt++)
#pragma unroll
        for (int nt = 0; nt < 8; nt++)
#pragma unroll
            for (int f = 0; f < 4; f++) oacc[mt][nt][f] = 0.f;
    float mrow[2][2] = {{-1e30f, -1e30f}, {-1e30f, -1e30f}};
    float lrow[2][2] = {{0.f, 0.f}, {0.f, 0.f}};

    for (int jb = 0; jb < 4; jb++) {
        float sacc[2][8][4];
#pragma unroll
        for (int mt = 0; mt < 2; mt++)
#pragma unroll
            for (int nt = 0; nt < 8; nt++)
#pragma unroll
                for (int f = 0; f < 4; f++) sacc[mt][nt][f] = 0.f;
#pragma unroll
        for (int ks = 0; ks < 8; ks++) {
            uint32_t kf[8][2];
#pragma unroll
            for (int nt = 0; nt < 8; nt++) {
                const float* p = Ks + (jb * 64 + nt * 8 + gid) * KSTR + ks * 8 + tig;
                kf[nt][0] = __float_as_uint(p[0]);
                kf[nt][1] = __float_as_uint(p[4]);
            }
#pragma unroll
            for (int mt = 0; mt < 2; mt++)
#pragma unroll
                for (int nt = 0; nt < 8; nt++)
                    mma_tf32(sacc[mt][nt], qf[mt][ks], kf[nt]);
        }

        __syncwarp();
#pragma unroll
        for (int mt = 0; mt < 2; mt++)
#pragma unroll
            for (int hh = 0; hh < 2; hh++) {
                float bm = -1e30f;
#pragma unroll
                for (int nt = 0; nt < 8; nt++) {
                    bm = fmaxf(bm, sacc[mt][nt][2 * hh]);
                    bm = fmaxf(bm, sacc[mt][nt][2 * hh + 1]);
                }
                bm = fmaxf(bm, __shfl_xor_sync(0xffffffffu, bm, 1));
                bm = fmaxf(bm, __shfl_xor_sync(0xffffffffu, bm, 2));
                float mn = fmaxf(mrow[mt][hh], bm);
                float scale = __expf(mrow[mt][hh] - mn);
                mrow[mt][hh] = mn;
                lrow[mt][hh] *= scale;
#pragma unroll
                for (int nt = 0; nt < 8; nt++) {
                    oacc[mt][nt][2 * hh]     *= scale;
                    oacc[mt][nt][2 * hh + 1] *= scale;
                }
                float psum = 0.f;
                int row = mt * 16 + gid + hh * 8;
#pragma unroll
                for (int nt = 0; nt < 8; nt++) {
                    float p0 = tf32r(__expf(sacc[mt][nt][2 * hh]     - mn));
                    float p1 = tf32r(__expf(sacc[mt][nt][2 * hh + 1] - mn));
                    psum += p0 + p1;
                    *(float2*)(Pw + row * KSTR + nt * 8 + 2 * tig) =
                        make_float2(p0, p1);
                }
                psum += __shfl_xor_sync(0xffffffffu, psum, 1);
                psum += __shfl_xor_sync(0xffffffffu, psum, 2);
                lrow[mt][hh] += psum;
            }
        __syncwarp();

#pragma unroll
        for (int ks = 0; ks < 8; ks++) {
            uint32_t pf[2][4], vf[8][2];
#pragma unroll
            for (int mt = 0; mt < 2; mt++) {
                const float* p = Pw + (mt * 16 + gid) * KSTR + ks * 8 + tig;
                pf[mt][0] = __float_as_uint(p[0]);
                pf[mt][1] = __float_as_uint(p[8 * KSTR]);
                pf[mt][2] = __float_as_uint(p[4]);
                pf[mt][3] = __float_as_uint(p[8 * KSTR + 4]);
            }
#pragma unroll
            for (int nt = 0; nt < 8; nt++) {
                const float* p = Vs + (jb * 64 + ks * 8 + tig) * VSTR + nt * 8 + gid;
                vf[nt][0] = __float_as_uint(p[0]);
                vf[nt][1] = __float_as_uint(p[4 * VSTR]);
            }
#pragma unroll
            for (int mt = 0; mt < 2; mt++)
#pragma unroll
                for (int nt = 0; nt < 8; nt++)
                    mma_tf32(oacc[mt][nt], pf[mt], vf[nt]);
        }
    }

    const int win = wh / 6, head = wh % 6;
#pragma unroll
    for (int mt = 0; mt < 2; mt++)
#pragma unroll
        for (int hh = 0; hh < 2; hh++) {
            float inv = 1.0f / lrow[mt][hh];
            int row = qr + mt * 16 + gid + hh * 8;
            bf16* op = out + ((size_t)win * 256 + row) * CDIM + head * 64;
#pragma unroll
            for (int nt = 0; nt < 8; nt++) {
                bf162 o = __floats2bfloat162_rn(
                    oacc[mt][nt][2 * hh] * inv,
                    oacc[mt][nt][2 * hh + 1] * inv);
                *(bf162*)(op + nt * 8 + 2 * tig) = o;
            }
        }
}

// ---------------------------------------------------------------------------
extern "C" void kernel_launch(void* const* d_in, const int* in_sizes, int n_in,
                              void* d_out, int out_size) {
    (void)in_sizes; (void)n_in; (void)out_size;
    const float* x   = (const float*)d_in[0];
    const float* Wq  = (const float*)d_in[1];
    const float* bq  = (const float*)d_in[2];
    const float* Wk  = (const float*)d_in[3];
    const float* bk  = (const float*)d_in[4];
    const float* Wv  = (const float*)d_in[5];
    const float* bv  = (const float*)d_in[6];
    const float* Wo  = (const float*)d_in[7];
    const float* bo  = (const float*)d_in[8];
    const float* g1  = (const float*)d_in[9];
    const float* be1 = (const float*)d_in[10];
    const float* g2  = (const float*)d_in[11];
    const float* be2 = (const float*)d_in[12];
    const float* W1  = (const float*)d_in[13];
    const float* B1  = (const float*)d_in[14];
    const float* W2  = (const float*)d_in[15];
    const float* B2  = (const float*)d_in[16];
    float* out = (float*)d_out;

    float *xw, *x2, *yb;
    bf16 *hb, *qb, *kb, *vb, *att, *mlp, *wt;
    cudaGetSymbolAddress((void**)&xw,  g_xw);
    cudaGetSymbolAddress((void**)&hb,  g_h);
    cudaGetSymbolAddress((void**)&qb,  g_q);
    cudaGetSymbolAddress((void**)&kb,  g_k);
    cudaGetSymbolAddress((void**)&vb,  g_v);
    cudaGetSymbolAddress((void**)&att, g_att);
    cudaGetSymbolAddress((void**)&x2,  g_x2);
    cudaGetSymbolAddress((void**)&mlp, g_mlp);
    cudaGetSymbolAddress((void**)&yb,  g_y);
    cudaGetSymbolAddress((void**)&wt,  g_wt);

    cudaFuncSetAttribute(attn_mma,
                         cudaFuncAttributeMaxDynamicSharedMemorySize, ATT_SMEM);

    // 0) weight transposes to K-major bf16
    transpose_kernel<<<dim3(12, 12), 256>>>(Wq, wt + 0,       CDIM, CDIM);
    transpose_kernel<<<dim3(12, 12), 256>>>(Wk, wt + 147456,  CDIM, CDIM);
    transpose_kernel<<<dim3(12, 12), 256>>>(Wv, wt + 294912,  CDIM, CDIM);
    transpose_kernel<<<dim3(12, 12), 256>>>(Wo, wt + 442368,  CDIM, CDIM);
    transpose_kernel<<<dim3(48, 12), 256>>>(W1, wt + 589824,  CDIM, MLPD);
    transpose_kernel<<<dim3(12, 48), 256>>>(W2, wt + 1179648, MLPD, CDIM);

    // 1) shift + window partition (fp32 residual stream)
    window_gather_kernel<<<dim3(12, 64, 16), 256>>>(x, xw);
    // 2) LN1 -> bf16
    ln_kernel<<<8192, 256>>>(xw, g1, be1, hb);
    // 3) QKV projections (bf16 mma + ldmatrix) -> bf16 [win][head][t][64]
    mm_qkv<<<dim3(3, 512, 3), 256>>>(hb, wt, bq, bk, bv, qb, kb, vb);
    // 4) windowed attention (tf32 mma flash, bf16 in/out)
    attn_mma<<<1536, 256, ATT_SMEM>>>(qb, kb, vb, att);
    // 5) output projection + residual -> fp32
    mm_biasres<<<dim3(3, 512), 256>>>(att, wt + 442368, bo, xw, x2, CDIM);
    // 6) LN2 -> bf16
    ln_kernel<<<8192, 256>>>(x2, g2, be2, hb);
    // 7) MLP up + GELU -> bf16
    mm_gelu<<<dim3(12, 512), 256>>>(hb, wt + 589824, B1, mlp);
    // 8) MLP down + residual -> fp32
    mm_biasres<<<dim3(3, 512), 256>>>(mlp, wt + 1179648, B2, x2, yb, MLPD);
    // 9) reverse window partition + shift
    window_scatter_kernel<<<dim3(12, 64, 16), 256>>>(yb, out);
}